// round 4
// baseline (speedup 1.0000x reference)
#include <cuda_runtime.h>

// Problem constants
#define B_SZ    2
#define S_LEN   2048
#define D_MODEL 1024
#define NHEAD   16
#define HD      64
#define M_ROWS  (B_SZ * S_LEN)      // 4096
#define QKV_LD  (3 * D_MODEL)       // 3072

// Scratch (device globals; no runtime allocation allowed)
__device__ float g_qkv [(size_t)M_ROWS * QKV_LD];   // [4096, 3072] : Q | K | V
__device__ float g_attn[(size_t)M_ROWS * D_MODEL];  // [4096, 1024] : attn out (B,S,H*HD)

// ---------------------------------------------------------------------------
// SGEMM (unchanged — ~49 TF/s, matched prediction):
// C[m,n] = sum_k A[m,k] * W[n,k] (+ bias[n])
// ---------------------------------------------------------------------------
template <bool HAS_BIAS>
__global__ void __launch_bounds__(256, 2) sgemm_xwT(
    const float* __restrict__ A, const float* __restrict__ W,
    const float* __restrict__ bias, float* __restrict__ C,
    int K, int ldc)
{
    __shared__ float As[2][16][132];
    __shared__ float Bs[2][16][132];

    const int tid = threadIdx.x;
    const int bm  = blockIdx.y * 128;
    const int bn  = blockIdx.x * 128;
    const int tr  = tid >> 4;
    const int tc  = tid & 15;

    const int r0 = tid >> 2;
    const int c4 = (tid & 3) * 4;

    const float* Ap = A + (size_t)(bm + r0) * K + c4;
    const float* Wp = W + (size_t)(bn + r0) * K + c4;
    const size_t rowskip = (size_t)64 * K;

    float acc[8][8];
#pragma unroll
    for (int i = 0; i < 8; i++)
#pragma unroll
        for (int j = 0; j < 8; j++) acc[i][j] = 0.f;

    {
        float4 pa0 = *reinterpret_cast<const float4*>(Ap);
        float4 pa1 = *reinterpret_cast<const float4*>(Ap + rowskip);
        float4 pb0 = *reinterpret_cast<const float4*>(Wp);
        float4 pb1 = *reinterpret_cast<const float4*>(Wp + rowskip);
        As[0][c4 + 0][r0] = pa0.x; As[0][c4 + 1][r0] = pa0.y;
        As[0][c4 + 2][r0] = pa0.z; As[0][c4 + 3][r0] = pa0.w;
        As[0][c4 + 0][r0 + 64] = pa1.x; As[0][c4 + 1][r0 + 64] = pa1.y;
        As[0][c4 + 2][r0 + 64] = pa1.z; As[0][c4 + 3][r0 + 64] = pa1.w;
        Bs[0][c4 + 0][r0] = pb0.x; Bs[0][c4 + 1][r0] = pb0.y;
        Bs[0][c4 + 2][r0] = pb0.z; Bs[0][c4 + 3][r0] = pb0.w;
        Bs[0][c4 + 0][r0 + 64] = pb1.x; Bs[0][c4 + 1][r0 + 64] = pb1.y;
        Bs[0][c4 + 2][r0 + 64] = pb1.z; Bs[0][c4 + 3][r0 + 64] = pb1.w;
    }
    __syncthreads();

    int buf = 0;
    for (int k0 = 16; k0 <= K; k0 += 16) {
        const bool more = (k0 < K);
        float4 pa0, pa1, pb0, pb1;
        if (more) {
            pa0 = *reinterpret_cast<const float4*>(Ap + k0);
            pa1 = *reinterpret_cast<const float4*>(Ap + k0 + rowskip);
            pb0 = *reinterpret_cast<const float4*>(Wp + k0);
            pb1 = *reinterpret_cast<const float4*>(Wp + k0 + rowskip);
        }

#pragma unroll
        for (int kk = 0; kk < 16; kk++) {
            float4 a0 = *reinterpret_cast<const float4*>(&As[buf][kk][tr * 4]);
            float4 a1 = *reinterpret_cast<const float4*>(&As[buf][kk][tr * 4 + 64]);
            float4 b0 = *reinterpret_cast<const float4*>(&Bs[buf][kk][tc * 4]);
            float4 b1 = *reinterpret_cast<const float4*>(&Bs[buf][kk][tc * 4 + 64]);
            float av[8] = {a0.x, a0.y, a0.z, a0.w, a1.x, a1.y, a1.z, a1.w};
            float bv[8] = {b0.x, b0.y, b0.z, b0.w, b1.x, b1.y, b1.z, b1.w};
#pragma unroll
            for (int i = 0; i < 8; i++)
#pragma unroll
                for (int j = 0; j < 8; j++)
                    acc[i][j] += av[i] * bv[j];
        }

        if (more) {
            const int nb = buf ^ 1;
            As[nb][c4 + 0][r0] = pa0.x; As[nb][c4 + 1][r0] = pa0.y;
            As[nb][c4 + 2][r0] = pa0.z; As[nb][c4 + 3][r0] = pa0.w;
            As[nb][c4 + 0][r0 + 64] = pa1.x; As[nb][c4 + 1][r0 + 64] = pa1.y;
            As[nb][c4 + 2][r0 + 64] = pa1.z; As[nb][c4 + 3][r0 + 64] = pa1.w;
            Bs[nb][c4 + 0][r0] = pb0.x; Bs[nb][c4 + 1][r0] = pb0.y;
            Bs[nb][c4 + 2][r0] = pb0.z; Bs[nb][c4 + 3][r0] = pb0.w;
            Bs[nb][c4 + 0][r0 + 64] = pb1.x; Bs[nb][c4 + 1][r0 + 64] = pb1.y;
            Bs[nb][c4 + 2][r0 + 64] = pb1.z; Bs[nb][c4 + 3][r0 + 64] = pb1.w;
        }
        __syncthreads();
        buf ^= 1;
    }

#pragma unroll
    for (int ih = 0; ih < 2; ih++) {
#pragma unroll
        for (int ii = 0; ii < 4; ii++) {
            const int m = bm + ih * 64 + tr * 4 + ii;
#pragma unroll
            for (int jh = 0; jh < 2; jh++) {
                const int n = bn + jh * 64 + tc * 4;
                float4 v;
                v.x = acc[ih * 4 + ii][jh * 4 + 0];
                v.y = acc[ih * 4 + ii][jh * 4 + 1];
                v.z = acc[ih * 4 + ii][jh * 4 + 2];
                v.w = acc[ih * 4 + ii][jh * 4 + 3];
                if (HAS_BIAS) {
                    v.x += bias[n + 0]; v.y += bias[n + 1];
                    v.z += bias[n + 2]; v.w += bias[n + 3];
                }
                *reinterpret_cast<float4*>(&C[(size_t)m * ldc + n]) = v;
            }
        }
    }
}

// ---------------------------------------------------------------------------
// Causal flash attention v4.
// Q-tile 128 x KV-tile 64. 256 threads = 32(ty) x 8(tx).
// Microtile 4 q-rows x 8 kv-cols (split {4tx..+3, 32+4tx..+3}).
// Pad-68 rows (no swizzle). K stored transposed. All inner-loop smem
// accesses are LDS.128, conflict-free per 8-lane phase.
// smem: Q[128][68] + Kt[64][68] + V[64][68] + P[128][68] = 104448 B.
// ---------------------------------------------------------------------------
#define LDP 68
#define SM_QS  0
#define SM_KT  (128 * LDP)                  // 8704
#define SM_VS  (SM_KT + 64 * LDP)           // 13056
#define SM_PS  (SM_VS + 64 * LDP)           // 17408
#define FLASH_SMEM_FLOATS (SM_PS + 128 * LDP)  // 26112 floats
#define FLASH_SMEM_BYTES  (FLASH_SMEM_FLOATS * 4)  // 104448

__global__ void __launch_bounds__(256, 2) flash_fwd(
    const float* __restrict__ qkv, float* __restrict__ attn)
{
    extern __shared__ float sm[];
    float* Qs = sm + SM_QS;   // [128 q][68]
    float* Kt = sm + SM_KT;   // [64 d][68 kcol] (transposed)
    float* Vs = sm + SM_VS;   // [64 kk][68 d]
    float* Ps = sm + SM_PS;   // [128 q][68 kcol]

    const int qt = (gridDim.x - 1) - blockIdx.x;  // longest tiles first
    const int h  = blockIdx.y;
    const int b  = blockIdx.z;
    const int tid = threadIdx.x;
    const int ty = tid >> 3;     // 0..31
    const int tx = tid & 7;      // 0..7
    const int q0 = ty * 4;
    const int cA = 4 * tx;       // owned col group A
    const int cB = 32 + 4 * tx;  // owned col group B

    const size_t head_base = (size_t)b * S_LEN * QKV_LD + (size_t)h * HD;

    // Load Q tile [128 x 64], pre-scaled by 1/8
#pragma unroll
    for (int t = 0; t < 8; t++) {
        const int fid = tid + t * 256;
        const int r = fid >> 4, gc = fid & 15;
        float4 v = *reinterpret_cast<const float4*>(
            &qkv[head_base + (size_t)(qt * 128 + r) * QKV_LD + gc * 4]);
        v.x *= 0.125f; v.y *= 0.125f; v.z *= 0.125f; v.w *= 0.125f;
        *reinterpret_cast<float4*>(&Qs[r * LDP + gc * 4]) = v;
    }

    float o[4][8];
    float mi[4], li[4];
#pragma unroll
    for (int i = 0; i < 4; i++) {
        mi[i] = -1e30f; li[i] = 0.f;
#pragma unroll
        for (int j = 0; j < 8; j++) o[i][j] = 0.f;
    }

    const int kt_end = 2 * qt + 1;
    for (int kt = 0; kt <= kt_end; kt++) {
        // Load K (transposed scalar stores) and V (float4 stores)
#pragma unroll
        for (int t = 0; t < 4; t++) {
            const int fid = tid + t * 256;
            const int r = fid >> 4, gc = fid & 15;
            const size_t g = head_base + (size_t)(kt * 64 + r) * QKV_LD + gc * 4;
            float4 kv = *reinterpret_cast<const float4*>(&qkv[g + D_MODEL]);
            float4 vv = *reinterpret_cast<const float4*>(&qkv[g + 2 * D_MODEL]);
            Kt[(4 * gc + 0) * LDP + r] = kv.x;
            Kt[(4 * gc + 1) * LDP + r] = kv.y;
            Kt[(4 * gc + 2) * LDP + r] = kv.z;
            Kt[(4 * gc + 3) * LDP + r] = kv.w;
            *reinterpret_cast<float4*>(&Vs[r * LDP + gc * 4]) = vv;
        }
        __syncthreads();

        // S = Q @ K^T : rows q0..+3, cols {cA..+3, cB..+3}
        float s[4][8];
#pragma unroll
        for (int i = 0; i < 4; i++)
#pragma unroll
            for (int j = 0; j < 8; j++) s[i][j] = 0.f;

#pragma unroll 2
        for (int d4 = 0; d4 < 16; d4++) {
            float4 aq[4];
#pragma unroll
            for (int i = 0; i < 4; i++)
                aq[i] = *reinterpret_cast<const float4*>(&Qs[(q0 + i) * LDP + 4 * d4]);
#pragma unroll
            for (int dd = 0; dd < 4; dd++) {
                const float* krow = &Kt[(4 * d4 + dd) * LDP];
                float4 kl = *reinterpret_cast<const float4*>(&krow[cA]);
                float4 kh = *reinterpret_cast<const float4*>(&krow[cB]);
#pragma unroll
                for (int i = 0; i < 4; i++) {
                    const float a = (dd == 0) ? aq[i].x : (dd == 1) ? aq[i].y
                                   : (dd == 2) ? aq[i].z : aq[i].w;
                    s[i][0] += a * kl.x; s[i][1] += a * kl.y;
                    s[i][2] += a * kl.z; s[i][3] += a * kl.w;
                    s[i][4] += a * kh.x; s[i][5] += a * kh.y;
                    s[i][6] += a * kh.z; s[i][7] += a * kh.w;
                }
            }
        }

        // Causal mask: only the top two kv tiles can cross the diagonal
        if (kt >= 2 * qt) {
            const int row0 = qt * 128 + q0;
#pragma unroll
            for (int i = 0; i < 4; i++) {
#pragma unroll
                for (int j = 0; j < 8; j++) {
                    const int colg = kt * 64 + ((j < 4) ? (cA + j) : (cB + j - 4));
                    if (colg > row0 + i) s[i][j] = -1e30f;
                }
            }
        }

        // Online softmax over the 8-lane tx group (s reused as P)
#pragma unroll
        for (int i = 0; i < 4; i++) {
            float rm = s[i][0];
#pragma unroll
            for (int j = 1; j < 8; j++) rm = fmaxf(rm, s[i][j]);
#pragma unroll
            for (int off = 4; off >= 1; off >>= 1)
                rm = fmaxf(rm, __shfl_xor_sync(0xffffffffu, rm, off));

            const float nm    = fmaxf(mi[i], rm);
            const float alpha = __expf(mi[i] - nm);
            mi[i] = nm;

            float sum = 0.f;
#pragma unroll
            for (int j = 0; j < 8; j++) {
                s[i][j] = __expf(s[i][j] - nm);
                sum += s[i][j];
            }
#pragma unroll
            for (int off = 4; off >= 1; off >>= 1)
                sum += __shfl_xor_sync(0xffffffffu, sum, off);

            li[i] = li[i] * alpha + sum;
#pragma unroll
            for (int j = 0; j < 8; j++) o[i][j] *= alpha;
        }

        // Stage P (two float4 stores per row)
#pragma unroll
        for (int i = 0; i < 4; i++) {
            float4 lo, hi;
            lo.x = s[i][0]; lo.y = s[i][1]; lo.z = s[i][2]; lo.w = s[i][3];
            hi.x = s[i][4]; hi.y = s[i][5]; hi.z = s[i][6]; hi.w = s[i][7];
            *reinterpret_cast<float4*>(&Ps[(q0 + i) * LDP + cA]) = lo;
            *reinterpret_cast<float4*>(&Ps[(q0 + i) * LDP + cB]) = hi;
        }
        __syncthreads();

        // O += P @ V : all LDS.128
#pragma unroll 2
        for (int k4 = 0; k4 < 16; k4++) {
            float4 pp[4];
#pragma unroll
            for (int i = 0; i < 4; i++)
                pp[i] = *reinterpret_cast<const float4*>(&Ps[(q0 + i) * LDP + 4 * k4]);
#pragma unroll
            for (int dd = 0; dd < 4; dd++) {
                const float* vrow = &Vs[(4 * k4 + dd) * LDP];
                float4 vl = *reinterpret_cast<const float4*>(&vrow[cA]);
                float4 vh = *reinterpret_cast<const float4*>(&vrow[cB]);
#pragma unroll
                for (int i = 0; i < 4; i++) {
                    const float p = (dd == 0) ? pp[i].x : (dd == 1) ? pp[i].y
                                   : (dd == 2) ? pp[i].z : pp[i].w;
                    o[i][0] += p * vl.x; o[i][1] += p * vl.y;
                    o[i][2] += p * vl.z; o[i][3] += p * vl.w;
                    o[i][4] += p * vh.x; o[i][5] += p * vh.y;
                    o[i][6] += p * vh.z; o[i][7] += p * vh.w;
                }
            }
        }
        __syncthreads();
    }

    // Normalize and write to [B, S, H*HD] — two float4 stores per row
    const size_t ob = ((size_t)b * S_LEN + qt * 128) * D_MODEL + (size_t)h * HD;
#pragma unroll
    for (int i = 0; i < 4; i++) {
        const float inv = 1.f / li[i];
        float4 lo, hi;
        lo.x = o[i][0] * inv; lo.y = o[i][1] * inv;
        lo.z = o[i][2] * inv; lo.w = o[i][3] * inv;
        hi.x = o[i][4] * inv; hi.y = o[i][5] * inv;
        hi.z = o[i][6] * inv; hi.w = o[i][7] * inv;
        float* orow = &attn[ob + (size_t)(q0 + i) * D_MODEL];
        *reinterpret_cast<float4*>(&orow[cA]) = lo;
        *reinterpret_cast<float4*>(&orow[cB]) = hi;
    }
}

// ---------------------------------------------------------------------------
extern "C" void kernel_launch(void* const* d_in, const int* in_sizes, int n_in,
                              void* d_out, int out_size)
{
    const float* x    = (const float*)d_in[0];
    const float* wq   = (const float*)d_in[1];
    const float* wk   = (const float*)d_in[2];
    const float* wv   = (const float*)d_in[3];
    const float* wo_w = (const float*)d_in[4];
    const float* wo_b = (const float*)d_in[5];
    float* out = (float*)d_out;

    float* qkv;  cudaGetSymbolAddress((void**)&qkv,  g_qkv);
    float* attn; cudaGetSymbolAddress((void**)&attn, g_attn);

    static bool attr_done = false;
    if (!attr_done) {
        cudaFuncSetAttribute(flash_fwd,
                             cudaFuncAttributeMaxDynamicSharedMemorySize,
                             FLASH_SMEM_BYTES);
        attr_done = true;
    }

    const dim3 gemm_blk(256);
    const dim3 gemm_grid(D_MODEL / 128, M_ROWS / 128);  // (8, 32)

    sgemm_xwT<false><<<gemm_grid, gemm_blk>>>(x, wq, nullptr, qkv + 0,           D_MODEL, QKV_LD);
    sgemm_xwT<false><<<gemm_grid, gemm_blk>>>(x, wk, nullptr, qkv + D_MODEL,     D_MODEL, QKV_LD);
    sgemm_xwT<false><<<gemm_grid, gemm_blk>>>(x, wv, nullptr, qkv + 2 * D_MODEL, D_MODEL, QKV_LD);

    const dim3 flash_grid(S_LEN / 128, NHEAD, B_SZ);  // (16, 16, 2)
    flash_fwd<<<flash_grid, 256, FLASH_SMEM_BYTES>>>(qkv, attn);

    sgemm_xwT<true><<<gemm_grid, gemm_blk>>>(attn, wo_w, wo_b, out, D_MODEL, D_MODEL);
}

// round 6
// speedup vs baseline: 1.4037x; 1.4037x over previous
#include <cuda_runtime.h>
#include <cuda_bf16.h>
#include <cstdint>

// Problem constants
#define B_SZ    2
#define S_LEN   2048
#define D_MODEL 1024
#define NHEAD   16
#define HD      64
#define M_ROWS  (B_SZ * S_LEN)      // 4096
#define QKV_LD  (3 * D_MODEL)       // 3072

// Scratch (device globals; no runtime allocation allowed)
__device__ float g_qkv [(size_t)M_ROWS * QKV_LD];   // [4096, 3072] : Q | K | V
__device__ float g_attn[(size_t)M_ROWS * D_MODEL];  // [4096, 1024]

__device__ __forceinline__ uint32_t smem_u32(const void* p) {
    uint32_t a;
    asm("{ .reg .u64 t; cvta.to.shared.u64 t, %1; cvt.u32.u64 %0, t; }"
        : "=r"(a) : "l"(p));
    return a;
}

#define LDM4(r, addr) \
    asm volatile("ldmatrix.sync.aligned.m8n8.x4.shared.b16 {%0,%1,%2,%3}, [%4];" \
        : "=r"((r)[0]), "=r"((r)[1]), "=r"((r)[2]), "=r"((r)[3]) : "r"(addr))

#define MMA_BF16(d, a, b0, b1) \
    asm volatile("mma.sync.aligned.m16n8k16.row.col.f32.bf16.bf16.f32 " \
        "{%0,%1,%2,%3}, {%4,%5,%6,%7}, {%8,%9}, {%0,%1,%2,%3};" \
        : "+f"((d)[0]), "+f"((d)[1]), "+f"((d)[2]), "+f"((d)[3]) \
        : "r"((a)[0]), "r"((a)[1]), "r"((a)[2]), "r"((a)[3]), "r"(b0), "r"(b1))

__device__ __forceinline__ uint32_t pack2(__nv_bfloat16 a, __nv_bfloat16 b) {
    return (uint32_t)__bfloat16_as_ushort(a) |
           ((uint32_t)__bfloat16_as_ushort(b) << 16);
}

// fp32x4 -> bf16 hi (rounded) + bf16 lo (residual)
__device__ __forceinline__ void cvt4(float4 v, uint2& h, uint2& l) {
    __nv_bfloat16 h0 = __float2bfloat16_rn(v.x);
    __nv_bfloat16 h1 = __float2bfloat16_rn(v.y);
    __nv_bfloat16 h2 = __float2bfloat16_rn(v.z);
    __nv_bfloat16 h3 = __float2bfloat16_rn(v.w);
    __nv_bfloat16 l0 = __float2bfloat16_rn(v.x - __bfloat162float(h0));
    __nv_bfloat16 l1 = __float2bfloat16_rn(v.y - __bfloat162float(h1));
    __nv_bfloat16 l2 = __float2bfloat16_rn(v.z - __bfloat162float(h2));
    __nv_bfloat16 l3 = __float2bfloat16_rn(v.w - __bfloat162float(h3));
    h.x = pack2(h0, h1); h.y = pack2(h2, h3);
    l.x = pack2(l0, l1); l.y = pack2(l2, l3);
}

// ===========================================================================
// mma.sync bf16x3 GEMM:  C[m,n] = sum_k A[m,k] * W[n,k] (+ bias[n])
// CTA 128x128, BK=32, 8 warps (2x4), warp tile 64x32, m16n8k16 frags.
// smem tiles bf16, rows padded to 40 elems (80 B, 20-bank stride =>
// conflict-free ldmatrix). Double-buffered: 2 stages x 40 KB = 80 KB.
// 3x split: Ah*Bh + Ah*Bl + Al*Bh.
// W selected from {W0,W1,W2} by blockIdx.x>>3 (fused QKV); output column
// base = (blockIdx.x>>3)*1024 + (blockIdx.x&7)*128.
// ===========================================================================
#define ROWB    80                       // bytes per padded bf16 row
#define T_AH    0
#define T_AL    10240
#define T_BH    20480
#define T_BL    30720
#define STAGE_B 40960
#define GEMM_SMEM_BYTES (2 * STAGE_B)    // 81920

template <bool HAS_BIAS>
__global__ void __launch_bounds__(256) mma_gemm(
    const float* __restrict__ A,
    const float* __restrict__ W0, const float* __restrict__ W1,
    const float* __restrict__ W2,
    const float* __restrict__ bias, float* __restrict__ C,
    int K, int ldc)
{
    extern __shared__ __align__(128) char smem[];
    const uint32_t sbase = smem_u32(smem);
    const int tid  = threadIdx.x;
    const int lane = tid & 31;
    const int bx   = blockIdx.x;
    const int bm   = blockIdx.y * 128;
    const int bn   = (bx & 7) * 128;                 // row block in W
    const int cn   = (bx >> 3) * D_MODEL + bn;       // output col base
    const float* W = (bx < 8) ? W0 : (bx < 16) ? W1 : W2;

    // Warp tiling
    const int wm = (tid >> 7) * 64;          // warp row offset (warps 0-3 / 4-7)
    const int wn = ((tid >> 5) & 3) * 32;    // warp col offset

    // ldmatrix per-lane byte offsets (within a tile)
    const uint32_t a_off = (uint32_t)(wm + (lane & 15)) * ROWB + ((lane >> 4) * 8) * 2;
    const uint32_t b_off = (uint32_t)(wn + (lane >> 4) * 8 + (lane & 7)) * ROWB
                           + (((lane >> 3) & 1) * 8) * 2;

    // Loader mapping: 4 float4 per matrix per chunk
    const int r0 = tid >> 3;        // 0..31 (+32 per t)
    const int gc = tid & 7;         // 16B granule (4 floats)
    const float* Ap = A + (size_t)(bm + r0) * K + gc * 4;
    const float* Wp = W + (size_t)(bn + r0) * K + gc * 4;
    const size_t tskip = (size_t)32 * K;

    float acc[4][4][4];
#pragma unroll
    for (int i = 0; i < 4; i++)
#pragma unroll
        for (int j = 0; j < 4; j++)
#pragma unroll
            for (int r = 0; r < 4; r++) acc[i][j][r] = 0.f;

    const int nch = K / 32;
    float4 pa[4], pb[4];

    // prologue: chunk 0 -> regs -> stage 0
#pragma unroll
    for (int t = 0; t < 4; t++) {
        pa[t] = *reinterpret_cast<const float4*>(Ap + t * tskip);
        pb[t] = *reinterpret_cast<const float4*>(Wp + t * tskip);
    }
    {
        char* st = smem;
#pragma unroll
        for (int t = 0; t < 4; t++) {
            const uint32_t off = (uint32_t)(r0 + 32 * t) * ROWB + gc * 8;
            uint2 h, l;
            cvt4(pa[t], h, l);
            *reinterpret_cast<uint2*>(st + T_AH + off) = h;
            *reinterpret_cast<uint2*>(st + T_AL + off) = l;
            cvt4(pb[t], h, l);
            *reinterpret_cast<uint2*>(st + T_BH + off) = h;
            *reinterpret_cast<uint2*>(st + T_BL + off) = l;
        }
    }
    __syncthreads();

    for (int c = 0; c < nch; c++) {
        const bool more = (c + 1 < nch);
        if (more) {
            const int k0 = (c + 1) * 32;
#pragma unroll
            for (int t = 0; t < 4; t++) {
                pa[t] = *reinterpret_cast<const float4*>(Ap + k0 + t * tskip);
                pb[t] = *reinterpret_cast<const float4*>(Wp + k0 + t * tskip);
            }
        }

        // compute on stage c&1
        const uint32_t stb = sbase + (c & 1) * STAGE_B;
#pragma unroll
        for (int kk = 0; kk < 2; kk++) {
            const uint32_t ko = kk * 32;   // 16 bf16 = 32 B
            uint32_t ah[4][4], al[4][4];
#pragma unroll
            for (int mf = 0; mf < 4; mf++) {
                LDM4(ah[mf], stb + T_AH + a_off + mf * (16 * ROWB) + ko);
                LDM4(al[mf], stb + T_AL + a_off + mf * (16 * ROWB) + ko);
            }
            uint32_t bh[2][4], bl[2][4];
#pragma unroll
            for (int p = 0; p < 2; p++) {
                LDM4(bh[p], stb + T_BH + b_off + p * (16 * ROWB) + ko);
                LDM4(bl[p], stb + T_BL + b_off + p * (16 * ROWB) + ko);
            }
#pragma unroll
            for (int mf = 0; mf < 4; mf++) {
#pragma unroll
                for (int nf = 0; nf < 4; nf++) {
                    const uint32_t b0h = bh[nf >> 1][(nf & 1) * 2];
                    const uint32_t b1h = bh[nf >> 1][(nf & 1) * 2 + 1];
                    const uint32_t b0l = bl[nf >> 1][(nf & 1) * 2];
                    const uint32_t b1l = bl[nf >> 1][(nf & 1) * 2 + 1];
                    MMA_BF16(acc[mf][nf], ah[mf], b0h, b1h);
                    MMA_BF16(acc[mf][nf], ah[mf], b0l, b1l);
                    MMA_BF16(acc[mf][nf], al[mf], b0h, b1h);
                }
            }
        }

        if (more) {
            char* st = smem + ((c + 1) & 1) * STAGE_B;
#pragma unroll
            for (int t = 0; t < 4; t++) {
                const uint32_t off = (uint32_t)(r0 + 32 * t) * ROWB + gc * 8;
                uint2 h, l;
                cvt4(pa[t], h, l);
                *reinterpret_cast<uint2*>(st + T_AH + off) = h;
                *reinterpret_cast<uint2*>(st + T_AL + off) = l;
                cvt4(pb[t], h, l);
                *reinterpret_cast<uint2*>(st + T_BH + off) = h;
                *reinterpret_cast<uint2*>(st + T_BL + off) = l;
            }
        }
        __syncthreads();
    }

    // Epilogue: fragment layout (g,2t),(g,2t+1),(g+8,2t),(g+8,2t+1)
    const int g  = lane >> 2;
    const int t2 = (lane & 3) * 2;
#pragma unroll
    for (int mf = 0; mf < 4; mf++) {
#pragma unroll
        for (int nf = 0; nf < 4; nf++) {
            const int m = bm + wm + mf * 16 + g;
            const int n = cn + wn + nf * 8 + t2;
            float2 v0, v1;
            v0.x = acc[mf][nf][0]; v0.y = acc[mf][nf][1];
            v1.x = acc[mf][nf][2]; v1.y = acc[mf][nf][3];
            if (HAS_BIAS) {
                const float2 bv = *reinterpret_cast<const float2*>(&bias[n]);
                v0.x += bv.x; v0.y += bv.y;
                v1.x += bv.x; v1.y += bv.y;
            }
            *reinterpret_cast<float2*>(&C[(size_t)m * ldc + n]) = v0;
            *reinterpret_cast<float2*>(&C[(size_t)(m + 8) * ldc + n]) = v1;
        }
    }
}

// ===========================================================================
// Causal flash attention (R3 version — best so far, unchanged)
// ===========================================================================
#define SM_QS  0
#define SM_KT  4096
#define SM_VS  8192
#define SM_PS  12288
#define FLASH_SMEM_BYTES (4 * 4096 * 4)   // 65536

__device__ __forceinline__ int fswz(int row, int g) {
    return row * 64 + (((g) ^ ((row >> 2) & 7)) << 2);
}

__global__ void __launch_bounds__(256) flash_fwd(
    const float* __restrict__ qkv, float* __restrict__ attn)
{
    extern __shared__ float sm[];
    float* Qs = sm + SM_QS;
    float* Kt = sm + SM_KT;
    float* Vs = sm + SM_VS;
    float* Ps = sm + SM_PS;

    const int qt = (gridDim.x - 1) - blockIdx.x;
    const int h  = blockIdx.y;
    const int b  = blockIdx.z;
    const int tid = threadIdx.x;
    const int ty = tid >> 4;
    const int tx = tid & 15;
    const int q0 = ty * 4;

    const size_t head_base = (size_t)b * S_LEN * QKV_LD + (size_t)h * HD;

#pragma unroll
    for (int t = 0; t < 4; t++) {
        const int fid = tid + t * 256;
        const int r = fid >> 4, gc = fid & 15;
        float4 v = *reinterpret_cast<const float4*>(
            &qkv[head_base + (size_t)(qt * 64 + r) * QKV_LD + gc * 4]);
        v.x *= 0.125f; v.y *= 0.125f; v.z *= 0.125f; v.w *= 0.125f;
        *reinterpret_cast<float4*>(&Qs[fswz(r, gc)]) = v;
    }

    float o[4][4];
    float mi[4], li[4];
#pragma unroll
    for (int i = 0; i < 4; i++) {
        mi[i] = -1e30f; li[i] = 0.f;
#pragma unroll
        for (int j = 0; j < 4; j++) o[i][j] = 0.f;
    }

    for (int kt = 0; kt <= qt; kt++) {
#pragma unroll
        for (int t = 0; t < 4; t++) {
            const int fid = tid + t * 256;
            const int r = fid >> 4, gc = fid & 15;
            const size_t g = head_base + (size_t)(kt * 64 + r) * QKV_LD + gc * 4;
            float4 kv = *reinterpret_cast<const float4*>(&qkv[g + D_MODEL]);
            float4 vv = *reinterpret_cast<const float4*>(&qkv[g + 2 * D_MODEL]);
            const int gk = ((r >> 2) ^ (gc & 7)) << 2;
            const int w  = r & 3;
            Kt[(4 * gc + 0) * 64 + gk + w] = kv.x;
            Kt[(4 * gc + 1) * 64 + gk + w] = kv.y;
            Kt[(4 * gc + 2) * 64 + gk + w] = kv.z;
            Kt[(4 * gc + 3) * 64 + gk + w] = kv.w;
            *reinterpret_cast<float4*>(&Vs[fswz(r, gc)]) = vv;
        }
        __syncthreads();

        float s[4][4];
#pragma unroll
        for (int i = 0; i < 4; i++)
#pragma unroll
            for (int j = 0; j < 4; j++) s[i][j] = 0.f;

#pragma unroll 4
        for (int d4 = 0; d4 < 16; d4++) {
            float4 aq[4], bk[4];
#pragma unroll
            for (int i = 0; i < 4; i++)
                aq[i] = *reinterpret_cast<const float4*>(&Qs[fswz(q0 + i, d4)]);
#pragma unroll
            for (int dd = 0; dd < 4; dd++)
                bk[dd] = *reinterpret_cast<const float4*>(
                    &Kt[(4 * d4 + dd) * 64 + ((tx ^ (d4 & 7)) << 2)]);
#pragma unroll
            for (int i = 0; i < 4; i++) {
                const float a0 = aq[i].x, a1 = aq[i].y, a2 = aq[i].z, a3 = aq[i].w;
                s[i][0] += a0 * bk[0].x; s[i][1] += a0 * bk[0].y;
                s[i][2] += a0 * bk[0].z; s[i][3] += a0 * bk[0].w;
                s[i][0] += a1 * bk[1].x; s[i][1] += a1 * bk[1].y;
                s[i][2] += a1 * bk[1].z; s[i][3] += a1 * bk[1].w;
                s[i][0] += a2 * bk[2].x; s[i][1] += a2 * bk[2].y;
                s[i][2] += a2 * bk[2].z; s[i][3] += a2 * bk[2].w;
                s[i][0] += a3 * bk[3].x; s[i][1] += a3 * bk[3].y;
                s[i][2] += a3 * bk[3].z; s[i][3] += a3 * bk[3].w;
            }
        }

        if (kt == qt) {
#pragma unroll
            for (int i = 0; i < 4; i++)
#pragma unroll
                for (int j = 0; j < 4; j++)
                    if (4 * tx + j > q0 + i) s[i][j] = -1e30f;
        }

#pragma unroll
        for (int i = 0; i < 4; i++) {
            float rm = fmaxf(fmaxf(s[i][0], s[i][1]), fmaxf(s[i][2], s[i][3]));
#pragma unroll
            for (int off = 8; off >= 1; off >>= 1)
                rm = fmaxf(rm, __shfl_xor_sync(0xffffffffu, rm, off));

            const float nm    = fmaxf(mi[i], rm);
            const float alpha = __expf(mi[i] - nm);
            mi[i] = nm;

            float sum = 0.f;
#pragma unroll
            for (int j = 0; j < 4; j++) {
                s[i][j] = __expf(s[i][j] - nm);
                sum += s[i][j];
            }
#pragma unroll
            for (int off = 8; off >= 1; off >>= 1)
                sum += __shfl_xor_sync(0xffffffffu, sum, off);

            li[i] = li[i] * alpha + sum;
#pragma unroll
            for (int j = 0; j < 4; j++) o[i][j] *= alpha;
        }

#pragma unroll
        for (int i = 0; i < 4; i++) {
            float4 v; v.x = s[i][0]; v.y = s[i][1]; v.z = s[i][2]; v.w = s[i][3];
            *reinterpret_cast<float4*>(&Ps[fswz(q0 + i, tx)]) = v;
        }
        __syncthreads();

#pragma unroll 4
        for (int k4 = 0; k4 < 16; k4++) {
            float4 pp[4], vv[4];
#pragma unroll
            for (int i = 0; i < 4; i++)
                pp[i] = *reinterpret_cast<const float4*>(&Ps[fswz(q0 + i, k4)]);
#pragma unroll
            for (int dd = 0; dd < 4; dd++)
                vv[dd] = *reinterpret_cast<const float4*>(
                    &Vs[(4 * k4 + dd) * 64 + ((tx ^ (k4 & 7)) << 2)]);
#pragma unroll
            for (int i = 0; i < 4; i++) {
                const float p0 = pp[i].x, p1 = pp[i].y, p2 = pp[i].z, p3 = pp[i].w;
                o[i][0] += p0 * vv[0].x; o[i][1] += p0 * vv[0].y;
                o[i][2] += p0 * vv[0].z; o[i][3] += p0 * vv[0].w;
                o[i][0] += p1 * vv[1].x; o[i][1] += p1 * vv[1].y;
                o[i][2] += p1 * vv[1].z; o[i][3] += p1 * vv[1].w;
                o[i][0] += p2 * vv[2].x; o[i][1] += p2 * vv[2].y;
                o[i][2] += p2 * vv[2].z; o[i][3] += p2 * vv[2].w;
                o[i][0] += p3 * vv[3].x; o[i][1] += p3 * vv[3].y;
                o[i][2] += p3 * vv[3].z; o[i][3] += p3 * vv[3].w;
            }
        }
        __syncthreads();
    }

    const size_t ob = ((size_t)b * S_LEN + qt * 64) * D_MODEL + (size_t)h * HD;
#pragma unroll
    for (int i = 0; i < 4; i++) {
        const float inv = 1.f / li[i];
        float4 v;
        v.x = o[i][0] * inv; v.y = o[i][1] * inv;
        v.z = o[i][2] * inv; v.w = o[i][3] * inv;
        *reinterpret_cast<float4*>(
            &attn[ob + (size_t)(q0 + i) * D_MODEL + 4 * tx]) = v;
    }
}

// ---------------------------------------------------------------------------
extern "C" void kernel_launch(void* const* d_in, const int* in_sizes, int n_in,
                              void* d_out, int out_size)
{
    const float* x    = (const float*)d_in[0];
    const float* wq   = (const float*)d_in[1];
    const float* wk   = (const float*)d_in[2];
    const float* wv   = (const float*)d_in[3];
    const float* wo_w = (const float*)d_in[4];
    const float* wo_b = (const float*)d_in[5];
    float* out = (float*)d_out;

    float* qkv;  cudaGetSymbolAddress((void**)&qkv,  g_qkv);
    float* attn; cudaGetSymbolAddress((void**)&attn, g_attn);

    static bool attr_done = false;
    if (!attr_done) {
        cudaFuncSetAttribute(flash_fwd,
                             cudaFuncAttributeMaxDynamicSharedMemorySize,
                             FLASH_SMEM_BYTES);
        cudaFuncSetAttribute(mma_gemm<false>,
                             cudaFuncAttributeMaxDynamicSharedMemorySize,
                             GEMM_SMEM_BYTES);
        cudaFuncSetAttribute(mma_gemm<true>,
                             cudaFuncAttributeMaxDynamicSharedMemorySize,
                             GEMM_SMEM_BYTES);
        attr_done = true;
    }

    // Fused QKV projection: grid.x covers wq | wk | wv column blocks
    const dim3 qkv_grid(24, M_ROWS / 128);   // (24, 32)
    mma_gemm<false><<<qkv_grid, 256, GEMM_SMEM_BYTES>>>(
        x, wq, wk, wv, nullptr, qkv, D_MODEL, QKV_LD);

    const dim3 flash_grid(S_LEN / 64, NHEAD, B_SZ);  // (32, 16, 2)
    flash_fwd<<<flash_grid, 256, FLASH_SMEM_BYTES>>>(qkv, attn);

    // Output projection with bias
    const dim3 o_grid(8, M_ROWS / 128);      // (8, 32)
    mma_gemm<true><<<o_grid, 256, GEMM_SMEM_BYTES>>>(
        attn, wo_w, wo_w, wo_w, wo_b, out, D_MODEL, D_MODEL);
}

// round 7
// speedup vs baseline: 2.1416x; 1.5257x over previous
#include <cuda_runtime.h>
#include <cuda_bf16.h>
#include <cstdint>

// Problem constants
#define B_SZ    2
#define S_LEN   2048
#define D_MODEL 1024
#define NHEAD   16
#define HD      64
#define M_ROWS  (B_SZ * S_LEN)      // 4096
#define QKV_LD  (3 * D_MODEL)       // 3072

__device__ float g_qkv [(size_t)M_ROWS * QKV_LD];   // [4096, 3072] : Q | K | V
__device__ float g_attn[(size_t)M_ROWS * D_MODEL];  // [4096, 1024]

__device__ __forceinline__ uint32_t smem_u32(const void* p) {
    uint32_t a;
    asm("{ .reg .u64 t; cvta.to.shared.u64 t, %1; cvt.u32.u64 %0, t; }"
        : "=r"(a) : "l"(p));
    return a;
}

#define LDM4(r, addr) \
    asm volatile("ldmatrix.sync.aligned.m8n8.x4.shared.b16 {%0,%1,%2,%3}, [%4];" \
        : "=r"((r)[0]), "=r"((r)[1]), "=r"((r)[2]), "=r"((r)[3]) : "r"(addr))

#define LDM4T(r, addr) \
    asm volatile("ldmatrix.sync.aligned.m8n8.x4.trans.shared.b16 {%0,%1,%2,%3}, [%4];" \
        : "=r"((r)[0]), "=r"((r)[1]), "=r"((r)[2]), "=r"((r)[3]) : "r"(addr))

#define MMA_BF16(d, a, b0, b1) \
    asm volatile("mma.sync.aligned.m16n8k16.row.col.f32.bf16.bf16.f32 " \
        "{%0,%1,%2,%3}, {%4,%5,%6,%7}, {%8,%9}, {%0,%1,%2,%3};" \
        : "+f"((d)[0]), "+f"((d)[1]), "+f"((d)[2]), "+f"((d)[3]) \
        : "r"((a)[0]), "r"((a)[1]), "r"((a)[2]), "r"((a)[3]), "r"(b0), "r"(b1))

__device__ __forceinline__ uint32_t pack2(__nv_bfloat16 a, __nv_bfloat16 b) {
    return (uint32_t)__bfloat16_as_ushort(a) |
           ((uint32_t)__bfloat16_as_ushort(b) << 16);
}

// fp32x4 -> bf16 hi (rounded) + bf16 lo (residual)
__device__ __forceinline__ void cvt4(float4 v, uint2& h, uint2& l) {
    __nv_bfloat16 h0 = __float2bfloat16_rn(v.x);
    __nv_bfloat16 h1 = __float2bfloat16_rn(v.y);
    __nv_bfloat16 h2 = __float2bfloat16_rn(v.z);
    __nv_bfloat16 h3 = __float2bfloat16_rn(v.w);
    __nv_bfloat16 l0 = __float2bfloat16_rn(v.x - __bfloat162float(h0));
    __nv_bfloat16 l1 = __float2bfloat16_rn(v.y - __bfloat162float(h1));
    __nv_bfloat16 l2 = __float2bfloat16_rn(v.z - __bfloat162float(h2));
    __nv_bfloat16 l3 = __float2bfloat16_rn(v.w - __bfloat162float(h3));
    h.x = pack2(h0, h1); h.y = pack2(h2, h3);
    l.x = pack2(l0, l1); l.y = pack2(l2, l3);
}

__device__ __forceinline__ uint32_t hi_lo_pack(float a, float b, uint32_t& lo) {
    __nv_bfloat16 ha = __float2bfloat16_rn(a);
    __nv_bfloat16 hb = __float2bfloat16_rn(b);
    lo = pack2(__float2bfloat16_rn(a - __bfloat162float(ha)),
               __float2bfloat16_rn(b - __bfloat162float(hb)));
    return pack2(ha, hb);
}

// ===========================================================================
// mma.sync bf16x3 GEMM (unchanged from R6 — 255 TF/s effective)
// ===========================================================================
#define ROWB    80
#define T_AH    0
#define T_AL    10240
#define T_BH    20480
#define T_BL    30720
#define STAGE_B 40960
#define GEMM_SMEM_BYTES (2 * STAGE_B)

template <bool HAS_BIAS>
__global__ void __launch_bounds__(256) mma_gemm(
    const float* __restrict__ A,
    const float* __restrict__ W0, const float* __restrict__ W1,
    const float* __restrict__ W2,
    const float* __restrict__ bias, float* __restrict__ C,
    int K, int ldc)
{
    extern __shared__ __align__(128) char smem[];
    const uint32_t sbase = smem_u32(smem);
    const int tid  = threadIdx.x;
    const int lane = tid & 31;
    const int bx   = blockIdx.x;
    const int bm   = blockIdx.y * 128;
    const int bn   = (bx & 7) * 128;
    const int cn   = (bx >> 3) * D_MODEL + bn;
    const float* W = (bx < 8) ? W0 : (bx < 16) ? W1 : W2;

    const int wm = (tid >> 7) * 64;
    const int wn = ((tid >> 5) & 3) * 32;

    const uint32_t a_off = (uint32_t)(wm + (lane & 15)) * ROWB + ((lane >> 4) * 8) * 2;
    const uint32_t b_off = (uint32_t)(wn + (lane >> 4) * 8 + (lane & 7)) * ROWB
                           + (((lane >> 3) & 1) * 8) * 2;

    const int r0 = tid >> 3;
    const int gc = tid & 7;
    const float* Ap = A + (size_t)(bm + r0) * K + gc * 4;
    const float* Wp = W + (size_t)(bn + r0) * K + gc * 4;
    const size_t tskip = (size_t)32 * K;

    float acc[4][4][4];
#pragma unroll
    for (int i = 0; i < 4; i++)
#pragma unroll
        for (int j = 0; j < 4; j++)
#pragma unroll
            for (int r = 0; r < 4; r++) acc[i][j][r] = 0.f;

    const int nch = K / 32;
    float4 pa[4], pb[4];

#pragma unroll
    for (int t = 0; t < 4; t++) {
        pa[t] = *reinterpret_cast<const float4*>(Ap + t * tskip);
        pb[t] = *reinterpret_cast<const float4*>(Wp + t * tskip);
    }
    {
        char* st = smem;
#pragma unroll
        for (int t = 0; t < 4; t++) {
            const uint32_t off = (uint32_t)(r0 + 32 * t) * ROWB + gc * 8;
            uint2 h, l;
            cvt4(pa[t], h, l);
            *reinterpret_cast<uint2*>(st + T_AH + off) = h;
            *reinterpret_cast<uint2*>(st + T_AL + off) = l;
            cvt4(pb[t], h, l);
            *reinterpret_cast<uint2*>(st + T_BH + off) = h;
            *reinterpret_cast<uint2*>(st + T_BL + off) = l;
        }
    }
    __syncthreads();

    for (int c = 0; c < nch; c++) {
        const bool more = (c + 1 < nch);
        if (more) {
            const int k0 = (c + 1) * 32;
#pragma unroll
            for (int t = 0; t < 4; t++) {
                pa[t] = *reinterpret_cast<const float4*>(Ap + k0 + t * tskip);
                pb[t] = *reinterpret_cast<const float4*>(Wp + k0 + t * tskip);
            }
        }

        const uint32_t stb = sbase + (c & 1) * STAGE_B;
#pragma unroll
        for (int kk = 0; kk < 2; kk++) {
            const uint32_t ko = kk * 32;
            uint32_t ah[4][4], al[4][4];
#pragma unroll
            for (int mf = 0; mf < 4; mf++) {
                LDM4(ah[mf], stb + T_AH + a_off + mf * (16 * ROWB) + ko);
                LDM4(al[mf], stb + T_AL + a_off + mf * (16 * ROWB) + ko);
            }
            uint32_t bh[2][4], bl[2][4];
#pragma unroll
            for (int p = 0; p < 2; p++) {
                LDM4(bh[p], stb + T_BH + b_off + p * (16 * ROWB) + ko);
                LDM4(bl[p], stb + T_BL + b_off + p * (16 * ROWB) + ko);
            }
#pragma unroll
            for (int mf = 0; mf < 4; mf++) {
#pragma unroll
                for (int nf = 0; nf < 4; nf++) {
                    const uint32_t b0h = bh[nf >> 1][(nf & 1) * 2];
                    const uint32_t b1h = bh[nf >> 1][(nf & 1) * 2 + 1];
                    const uint32_t b0l = bl[nf >> 1][(nf & 1) * 2];
                    const uint32_t b1l = bl[nf >> 1][(nf & 1) * 2 + 1];
                    MMA_BF16(acc[mf][nf], ah[mf], b0h, b1h);
                    MMA_BF16(acc[mf][nf], ah[mf], b0l, b1l);
                    MMA_BF16(acc[mf][nf], al[mf], b0h, b1h);
                }
            }
        }

        if (more) {
            char* st = smem + ((c + 1) & 1) * STAGE_B;
#pragma unroll
            for (int t = 0; t < 4; t++) {
                const uint32_t off = (uint32_t)(r0 + 32 * t) * ROWB + gc * 8;
                uint2 h, l;
                cvt4(pa[t], h, l);
                *reinterpret_cast<uint2*>(st + T_AH + off) = h;
                *reinterpret_cast<uint2*>(st + T_AL + off) = l;
                cvt4(pb[t], h, l);
                *reinterpret_cast<uint2*>(st + T_BH + off) = h;
                *reinterpret_cast<uint2*>(st + T_BL + off) = l;
            }
        }
        __syncthreads();
    }

    const int g  = lane >> 2;
    const int t2 = (lane & 3) * 2;
#pragma unroll
    for (int mf = 0; mf < 4; mf++) {
#pragma unroll
        for (int nf = 0; nf < 4; nf++) {
            const int m = bm + wm + mf * 16 + g;
            const int n = cn + wn + nf * 8 + t2;
            float2 v0, v1;
            v0.x = acc[mf][nf][0]; v0.y = acc[mf][nf][1];
            v1.x = acc[mf][nf][2]; v1.y = acc[mf][nf][3];
            if (HAS_BIAS) {
                const float2 bv = *reinterpret_cast<const float2*>(&bias[n]);
                v0.x += bv.x; v0.y += bv.y;
                v1.x += bv.x; v1.y += bv.y;
            }
            *reinterpret_cast<float2*>(&C[(size_t)m * ldc + n]) = v0;
            *reinterpret_cast<float2*>(&C[(size_t)(m + 8) * ldc + n]) = v1;
        }
    }
}

// ===========================================================================
// Tensor-core causal flash attention (mma.sync bf16 x3 split).
// CTA: 128 q-rows x (head, batch); 256 thr = 8 warps x 16 q-rows.
// Q held in registers as hi/lo A-fragments. K/V bf16 hi/lo in smem,
// 144B rows (9-granule stride -> conflict-free ldmatrix). P converts
// in-register (C-frag == A-frag layout). V consumed via ldmatrix.trans.
// ===========================================================================
#define FROWB 144                       // bytes per 64-elem bf16 row (+pad)
#define SQH   0
#define SQL   18432
#define SKH   0
#define SKL   9216
#define SVH   18432
#define SVL   27648
#define FLASH_SMEM_BYTES 36864

__global__ void __launch_bounds__(256) flash_mma(
    const float* __restrict__ qkv, float* __restrict__ attn)
{
    extern __shared__ __align__(128) char smem[];
    const uint32_t sbase = smem_u32(smem);
    const int tid  = threadIdx.x;
    const int lane = tid & 31;
    const int w    = tid >> 5;           // warp 0..7
    const int qt   = (gridDim.x - 1) - blockIdx.x;
    const int h    = blockIdx.y;
    const int b    = blockIdx.z;

    const size_t head_base = (size_t)b * S_LEN * QKV_LD + (size_t)h * HD;

    // ---- Stage Q (scaled by 1/8) as bf16 hi/lo, then load A-fragments ----
    {
        const int r = tid >> 1;                  // 0..127
        const int gq = (tid & 1) * 8;            // two float4 granule groups
#pragma unroll
        for (int t = 0; t < 8; t++) {
            const int gg = gq + t;               // granule 0..15
            float4 v = *reinterpret_cast<const float4*>(
                &qkv[head_base + (size_t)(qt * 128 + r) * QKV_LD + gg * 4]);
            v.x *= 0.125f; v.y *= 0.125f; v.z *= 0.125f; v.w *= 0.125f;
            uint2 hh, ll;
            cvt4(v, hh, ll);
            const uint32_t off = (uint32_t)r * FROWB + gg * 8;
            *reinterpret_cast<uint2*>(smem + SQH + off) = hh;
            *reinterpret_cast<uint2*>(smem + SQL + off) = ll;
        }
    }
    __syncthreads();

    uint32_t qh[4][4], ql[4][4];
    {
        const uint32_t a_off = (uint32_t)(w * 16 + (lane & 15)) * FROWB
                               + ((lane >> 4) * 8) * 2;
#pragma unroll
        for (int ks = 0; ks < 4; ks++) {
            LDM4(qh[ks], sbase + SQH + a_off + ks * 32);
            LDM4(ql[ks], sbase + SQL + a_off + ks * 32);
        }
    }
    __syncthreads();   // Q staging region is reused for K/V below

    float o[8][4];
#pragma unroll
    for (int nf = 0; nf < 8; nf++)
#pragma unroll
        for (int r = 0; r < 4; r++) o[nf][r] = 0.f;
    float m0 = -1e30f, m1 = -1e30f, l0 = 0.f, l1 = 0.f;

    const int g  = lane >> 2;
    const int t2 = (lane & 3) * 2;
    const int wrow = qt * 128 + w * 16;          // warp's first q row (global)
    const int row0 = wrow + g;
    const int row1 = row0 + 8;

    const uint32_t kb_off = (uint32_t)((lane >> 4) * 8 + (lane & 7)) * FROWB
                            + (((lane >> 3) & 1) * 8) * 2;
    const uint32_t vt_row = (uint32_t)(lane & 15) * FROWB + ((lane >> 4) * 8) * 2;

    const int kt_end = 2 * qt + 1;
    for (int kt = 0; kt <= kt_end; kt++) {
        // ---- Load K,V tile (64x64) as bf16 hi/lo ----
        {
            const int r = tid >> 2;              // 0..63
            const int gq = (tid & 3) * 4;        // granule base
#pragma unroll
            for (int t = 0; t < 4; t++) {
                const int gg = gq + t;
                const size_t gaddr = head_base
                    + (size_t)(kt * 64 + r) * QKV_LD + gg * 4;
                float4 kv = *reinterpret_cast<const float4*>(&qkv[gaddr + D_MODEL]);
                float4 vv = *reinterpret_cast<const float4*>(&qkv[gaddr + 2 * D_MODEL]);
                const uint32_t off = (uint32_t)r * FROWB + gg * 8;
                uint2 hh, ll;
                cvt4(kv, hh, ll);
                *reinterpret_cast<uint2*>(smem + SKH + off) = hh;
                *reinterpret_cast<uint2*>(smem + SKL + off) = ll;
                cvt4(vv, hh, ll);
                *reinterpret_cast<uint2*>(smem + SVH + off) = hh;
                *reinterpret_cast<uint2*>(smem + SVL + off) = ll;
            }
        }
        __syncthreads();

        const bool active = (kt * 64 <= wrow + 15);
        if (active) {
            // ---- Scores: S = Q @ K^T (3-term split) ----
            float s[8][4];
#pragma unroll
            for (int nf = 0; nf < 8; nf++)
#pragma unroll
                for (int r = 0; r < 4; r++) s[nf][r] = 0.f;

#pragma unroll
            for (int ks = 0; ks < 4; ks++) {
#pragma unroll
                for (int p = 0; p < 4; p++) {
                    uint32_t kh[4], kl[4];
                    LDM4(kh, sbase + SKH + kb_off + p * (16 * FROWB) + ks * 32);
                    LDM4(kl, sbase + SKL + kb_off + p * (16 * FROWB) + ks * 32);
                    MMA_BF16(s[2 * p],     qh[ks], kh[0], kh[1]);
                    MMA_BF16(s[2 * p],     qh[ks], kl[0], kl[1]);
                    MMA_BF16(s[2 * p],     ql[ks], kh[0], kh[1]);
                    MMA_BF16(s[2 * p + 1], qh[ks], kh[2], kh[3]);
                    MMA_BF16(s[2 * p + 1], qh[ks], kl[2], kl[3]);
                    MMA_BF16(s[2 * p + 1], ql[ks], kh[2], kh[3]);
                }
            }

            // ---- Causal mask ----
            if (kt * 64 + 63 > wrow) {
#pragma unroll
                for (int nf = 0; nf < 8; nf++) {
                    const int c0 = kt * 64 + nf * 8 + t2;
                    if (c0     > row0) s[nf][0] = -1e30f;
                    if (c0 + 1 > row0) s[nf][1] = -1e30f;
                    if (c0     > row1) s[nf][2] = -1e30f;
                    if (c0 + 1 > row1) s[nf][3] = -1e30f;
                }
            }

            // ---- Online softmax (rows g, g+8; quad reduce over t) ----
            float mx0 = s[0][0], mx1 = s[0][2];
#pragma unroll
            for (int nf = 0; nf < 8; nf++) {
                mx0 = fmaxf(mx0, fmaxf(s[nf][0], s[nf][1]));
                mx1 = fmaxf(mx1, fmaxf(s[nf][2], s[nf][3]));
            }
            mx0 = fmaxf(mx0, __shfl_xor_sync(0xffffffffu, mx0, 1));
            mx0 = fmaxf(mx0, __shfl_xor_sync(0xffffffffu, mx0, 2));
            mx1 = fmaxf(mx1, __shfl_xor_sync(0xffffffffu, mx1, 1));
            mx1 = fmaxf(mx1, __shfl_xor_sync(0xffffffffu, mx1, 2));

            const float nm0 = fmaxf(m0, mx0), nm1 = fmaxf(m1, mx1);
            const float a0 = __expf(m0 - nm0), a1 = __expf(m1 - nm1);
            m0 = nm0; m1 = nm1;

            float sum0 = 0.f, sum1 = 0.f;
#pragma unroll
            for (int nf = 0; nf < 8; nf++) {
                s[nf][0] = __expf(s[nf][0] - nm0);
                s[nf][1] = __expf(s[nf][1] - nm0);
                s[nf][2] = __expf(s[nf][2] - nm1);
                s[nf][3] = __expf(s[nf][3] - nm1);
                sum0 += s[nf][0] + s[nf][1];
                sum1 += s[nf][2] + s[nf][3];
            }
            sum0 += __shfl_xor_sync(0xffffffffu, sum0, 1);
            sum0 += __shfl_xor_sync(0xffffffffu, sum0, 2);
            sum1 += __shfl_xor_sync(0xffffffffu, sum1, 1);
            sum1 += __shfl_xor_sync(0xffffffffu, sum1, 2);
            l0 = l0 * a0 + sum0;
            l1 = l1 * a1 + sum1;

#pragma unroll
            for (int nf = 0; nf < 8; nf++) {
                o[nf][0] *= a0; o[nf][1] *= a0;
                o[nf][2] *= a1; o[nf][3] *= a1;
            }

            // ---- PV: O += P @ V (P in-register A-frags, V via ldmatrix.trans) ----
#pragma unroll
            for (int j = 0; j < 4; j++) {
                uint32_t ph[4], pl[4];
                ph[0] = hi_lo_pack(s[2 * j][0],     s[2 * j][1],     pl[0]);
                ph[1] = hi_lo_pack(s[2 * j][2],     s[2 * j][3],     pl[1]);
                ph[2] = hi_lo_pack(s[2 * j + 1][0], s[2 * j + 1][1], pl[2]);
                ph[3] = hi_lo_pack(s[2 * j + 1][2], s[2 * j + 1][3], pl[3]);

                const uint32_t vbase = (uint32_t)(j * 16) * FROWB + vt_row;
#pragma unroll
                for (int hg = 0; hg < 4; hg++) {
                    uint32_t vh[4], vl[4];
                    LDM4T(vh, sbase + SVH + vbase + hg * 32);
                    LDM4T(vl, sbase + SVL + vbase + hg * 32);
                    MMA_BF16(o[2 * hg],     ph, vh[0], vh[1]);
                    MMA_BF16(o[2 * hg],     ph, vl[0], vl[1]);
                    MMA_BF16(o[2 * hg],     pl, vh[0], vh[1]);
                    MMA_BF16(o[2 * hg + 1], ph, vh[2], vh[3]);
                    MMA_BF16(o[2 * hg + 1], ph, vl[2], vl[3]);
                    MMA_BF16(o[2 * hg + 1], pl, vh[2], vh[3]);
                }
            }
        }
        __syncthreads();
    }

    // ---- Normalize and write [B,S,H*HD] ----
    const float inv0 = 1.f / l0, inv1 = 1.f / l1;
    const size_t ob = ((size_t)b * S_LEN + qt * 128 + w * 16) * D_MODEL
                      + (size_t)h * HD;
#pragma unroll
    for (int nf = 0; nf < 8; nf++) {
        const int c = nf * 8 + t2;
        float2 v0, v1;
        v0.x = o[nf][0] * inv0; v0.y = o[nf][1] * inv0;
        v1.x = o[nf][2] * inv1; v1.y = o[nf][3] * inv1;
        *reinterpret_cast<float2*>(&attn[ob + (size_t)g * D_MODEL + c]) = v0;
        *reinterpret_cast<float2*>(&attn[ob + (size_t)(g + 8) * D_MODEL + c]) = v1;
    }
}

// ---------------------------------------------------------------------------
extern "C" void kernel_launch(void* const* d_in, const int* in_sizes, int n_in,
                              void* d_out, int out_size)
{
    const float* x    = (const float*)d_in[0];
    const float* wq   = (const float*)d_in[1];
    const float* wk   = (const float*)d_in[2];
    const float* wv   = (const float*)d_in[3];
    const float* wo_w = (const float*)d_in[4];
    const float* wo_b = (const float*)d_in[5];
    float* out = (float*)d_out;

    float* qkv;  cudaGetSymbolAddress((void**)&qkv,  g_qkv);
    float* attn; cudaGetSymbolAddress((void**)&attn, g_attn);

    static bool attr_done = false;
    if (!attr_done) {
        cudaFuncSetAttribute(mma_gemm<false>,
                             cudaFuncAttributeMaxDynamicSharedMemorySize,
                             GEMM_SMEM_BYTES);
        cudaFuncSetAttribute(mma_gemm<true>,
                             cudaFuncAttributeMaxDynamicSharedMemorySize,
                             GEMM_SMEM_BYTES);
        attr_done = true;
    }

    // Fused QKV projection
    const dim3 qkv_grid(24, M_ROWS / 128);
    mma_gemm<false><<<qkv_grid, 256, GEMM_SMEM_BYTES>>>(
        x, wq, wk, wv, nullptr, qkv, D_MODEL, QKV_LD);

    // Tensor-core causal flash attention
    const dim3 flash_grid(S_LEN / 128, NHEAD, B_SZ);  // (16, 16, 2)
    flash_mma<<<flash_grid, 256, FLASH_SMEM_BYTES>>>(qkv, attn);

    // Output projection with bias
    const dim3 o_grid(8, M_ROWS / 128);
    mma_gemm<true><<<o_grid, 256, GEMM_SMEM_BYTES>>>(
        attn, wo_w, wo_w, wo_w, wo_b, out, D_MODEL, D_MODEL);
}

// round 8
// speedup vs baseline: 2.3122x; 1.0797x over previous
#include <cuda_runtime.h>
#include <cuda_bf16.h>
#include <cstdint>

#define B_SZ    2
#define S_LEN   2048
#define D_MODEL 1024
#define NHEAD   16
#define HD      64
#define M_ROWS  (B_SZ * S_LEN)      // 4096
#define QKV_LD  (3 * D_MODEL)       // 3072

// bf16 hi/lo scratch (device globals)
__device__ __nv_bfloat16 g_xh [(size_t)M_ROWS * D_MODEL];
__device__ __nv_bfloat16 g_xl [(size_t)M_ROWS * D_MODEL];
__device__ __nv_bfloat16 g_wh [(size_t)3 * D_MODEL * D_MODEL];  // wq|wk|wv
__device__ __nv_bfloat16 g_wl [(size_t)3 * D_MODEL * D_MODEL];
__device__ __nv_bfloat16 g_woh[(size_t)D_MODEL * D_MODEL];
__device__ __nv_bfloat16 g_wol[(size_t)D_MODEL * D_MODEL];
__device__ __nv_bfloat16 g_qkvh[(size_t)M_ROWS * QKV_LD];       // Q(x0.125)|K|V
__device__ __nv_bfloat16 g_qkvl[(size_t)M_ROWS * QKV_LD];
__device__ __nv_bfloat16 g_atth[(size_t)M_ROWS * D_MODEL];
__device__ __nv_bfloat16 g_attl[(size_t)M_ROWS * D_MODEL];

__device__ __forceinline__ uint32_t smem_u32(const void* p) {
    uint32_t a;
    asm("{ .reg .u64 t; cvta.to.shared.u64 t, %1; cvt.u32.u64 %0, t; }"
        : "=r"(a) : "l"(p));
    return a;
}

#define LDM4(r, addr) \
    asm volatile("ldmatrix.sync.aligned.m8n8.x4.shared.b16 {%0,%1,%2,%3}, [%4];" \
        : "=r"((r)[0]), "=r"((r)[1]), "=r"((r)[2]), "=r"((r)[3]) : "r"(addr))

#define LDM4T(r, addr) \
    asm volatile("ldmatrix.sync.aligned.m8n8.x4.trans.shared.b16 {%0,%1,%2,%3}, [%4];" \
        : "=r"((r)[0]), "=r"((r)[1]), "=r"((r)[2]), "=r"((r)[3]) : "r"(addr))

#define MMA_BF16(d, a, b0, b1) \
    asm volatile("mma.sync.aligned.m16n8k16.row.col.f32.bf16.bf16.f32 " \
        "{%0,%1,%2,%3}, {%4,%5,%6,%7}, {%8,%9}, {%0,%1,%2,%3};" \
        : "+f"((d)[0]), "+f"((d)[1]), "+f"((d)[2]), "+f"((d)[3]) \
        : "r"((a)[0]), "r"((a)[1]), "r"((a)[2]), "r"((a)[3]), "r"(b0), "r"(b1))

__device__ __forceinline__ uint32_t pack2(__nv_bfloat16 a, __nv_bfloat16 b) {
    return (uint32_t)__bfloat16_as_ushort(a) |
           ((uint32_t)__bfloat16_as_ushort(b) << 16);
}

__device__ __forceinline__ void cvt4(float4 v, uint2& h, uint2& l) {
    __nv_bfloat16 h0 = __float2bfloat16_rn(v.x);
    __nv_bfloat16 h1 = __float2bfloat16_rn(v.y);
    __nv_bfloat16 h2 = __float2bfloat16_rn(v.z);
    __nv_bfloat16 h3 = __float2bfloat16_rn(v.w);
    __nv_bfloat16 l0 = __float2bfloat16_rn(v.x - __bfloat162float(h0));
    __nv_bfloat16 l1 = __float2bfloat16_rn(v.y - __bfloat162float(h1));
    __nv_bfloat16 l2 = __float2bfloat16_rn(v.z - __bfloat162float(h2));
    __nv_bfloat16 l3 = __float2bfloat16_rn(v.w - __bfloat162float(h3));
    h.x = pack2(h0, h1); h.y = pack2(h2, h3);
    l.x = pack2(l0, l1); l.y = pack2(l2, l3);
}

__device__ __forceinline__ uint32_t hi_lo_pack(float a, float b, uint32_t& lo) {
    __nv_bfloat16 ha = __float2bfloat16_rn(a);
    __nv_bfloat16 hb = __float2bfloat16_rn(b);
    lo = pack2(__float2bfloat16_rn(a - __bfloat162float(ha)),
               __float2bfloat16_rn(b - __bfloat162float(hb)));
    return pack2(ha, hb);
}

// ---------------------------------------------------------------------------
// One-shot f32 -> bf16 hi/lo conversion
// ---------------------------------------------------------------------------
__global__ void cvt_hl(const float* __restrict__ src,
                       __nv_bfloat16* __restrict__ h,
                       __nv_bfloat16* __restrict__ l, int n4)
{
    const int i = blockIdx.x * blockDim.x + threadIdx.x;
    if (i < n4) {
        float4 v = reinterpret_cast<const float4*>(src)[i];
        uint2 hh, ll;
        cvt4(v, hh, ll);
        reinterpret_cast<uint2*>(h)[i] = hh;
        reinterpret_cast<uint2*>(l)[i] = ll;
    }
}

// ===========================================================================
// mma.sync bf16x3 GEMM, pre-split inputs. C = A @ W^T (+bias).
// A,W given as bf16 hi/lo. Optional bf16 hi/lo output (with Q scale).
// CTA 128x128, BK=32, reg double-buffer, 8 warps, warp tile 64x32.
// ===========================================================================
#define ROWB    80
#define T_AH    0
#define T_AL    10240
#define T_BH    20480
#define T_BL    30720
#define STAGE_B 40960
#define GEMM_SMEM_BYTES (2 * STAGE_B)

template <bool HAS_BIAS, bool OUT_BF16, bool SCALE_Q8>
__global__ void __launch_bounds__(256) mma_gemm(
    const __nv_bfloat16* __restrict__ Ah, const __nv_bfloat16* __restrict__ Al,
    const __nv_bfloat16* __restrict__ Wh, const __nv_bfloat16* __restrict__ Wl,
    const float* __restrict__ bias,
    float* __restrict__ C,
    __nv_bfloat16* __restrict__ Ch, __nv_bfloat16* __restrict__ Cl,
    int K, int ldc)
{
    extern __shared__ __align__(128) char smem[];
    const uint32_t sbase = smem_u32(smem);
    const int tid  = threadIdx.x;
    const int lane = tid & 31;
    const int bx   = blockIdx.x;
    const int bm   = blockIdx.y * 128;
    const int bn   = (bx & 7) * 128;
    const int cn   = (bx >> 3) * D_MODEL + bn;
    const size_t woff = (size_t)(bx >> 3) * D_MODEL * D_MODEL;

    const int wm = (tid >> 7) * 64;
    const int wn = ((tid >> 5) & 3) * 32;

    const uint32_t a_off = (uint32_t)(wm + (lane & 15)) * ROWB + ((lane >> 4) * 8) * 2;
    const uint32_t b_off = (uint32_t)(wn + (lane >> 4) * 8 + (lane & 7)) * ROWB
                           + (((lane >> 3) & 1) * 8) * 2;

    // Loader: thread -> row lr, two 16B quarters (lq, lq+1)
    const int lr = tid >> 1;
    const int lq = (tid & 1) * 2;
    const __nv_bfloat16* pAh = Ah + (size_t)(bm + lr) * K;
    const __nv_bfloat16* pAl = Al + (size_t)(bm + lr) * K;
    const __nv_bfloat16* pWh = Wh + woff + (size_t)(bn + lr) * K;
    const __nv_bfloat16* pWl = Wl + woff + (size_t)(bn + lr) * K;
    const uint32_t soff0 = (uint32_t)lr * ROWB + lq * 16;

    float acc[4][4][4];
#pragma unroll
    for (int i = 0; i < 4; i++)
#pragma unroll
        for (int j = 0; j < 4; j++)
#pragma unroll
            for (int r = 0; r < 4; r++) acc[i][j][r] = 0.f;

    const int nch = K / 32;
    uint4 rAh[2], rAl[2], rWh[2], rWl[2];

    // prologue: chunk 0 -> stage 0
#pragma unroll
    for (int j = 0; j < 2; j++) {
        const int eo = (lq + j) * 8;
        rAh[j] = *reinterpret_cast<const uint4*>(pAh + eo);
        rAl[j] = *reinterpret_cast<const uint4*>(pAl + eo);
        rWh[j] = *reinterpret_cast<const uint4*>(pWh + eo);
        rWl[j] = *reinterpret_cast<const uint4*>(pWl + eo);
    }
#pragma unroll
    for (int j = 0; j < 2; j++) {
        const uint32_t o = soff0 + j * 16;
        *reinterpret_cast<uint4*>(smem + T_AH + o) = rAh[j];
        *reinterpret_cast<uint4*>(smem + T_AL + o) = rAl[j];
        *reinterpret_cast<uint4*>(smem + T_BH + o) = rWh[j];
        *reinterpret_cast<uint4*>(smem + T_BL + o) = rWl[j];
    }
    __syncthreads();

    for (int c = 0; c < nch; c++) {
        const bool more = (c + 1 < nch);
        if (more) {
            const int k0 = (c + 1) * 32;
#pragma unroll
            for (int j = 0; j < 2; j++) {
                const int eo = k0 + (lq + j) * 8;
                rAh[j] = *reinterpret_cast<const uint4*>(pAh + eo);
                rAl[j] = *reinterpret_cast<const uint4*>(pAl + eo);
                rWh[j] = *reinterpret_cast<const uint4*>(pWh + eo);
                rWl[j] = *reinterpret_cast<const uint4*>(pWl + eo);
            }
        }

        const uint32_t stb = sbase + (c & 1) * STAGE_B;
#pragma unroll
        for (int kk = 0; kk < 2; kk++) {
            const uint32_t ko = kk * 32;
            uint32_t ah[4][4], al[4][4];
#pragma unroll
            for (int mf = 0; mf < 4; mf++) {
                LDM4(ah[mf], stb + T_AH + a_off + mf * (16 * ROWB) + ko);
                LDM4(al[mf], stb + T_AL + a_off + mf * (16 * ROWB) + ko);
            }
            uint32_t bh[2][4], bl[2][4];
#pragma unroll
            for (int p = 0; p < 2; p++) {
                LDM4(bh[p], stb + T_BH + b_off + p * (16 * ROWB) + ko);
                LDM4(bl[p], stb + T_BL + b_off + p * (16 * ROWB) + ko);
            }
#pragma unroll
            for (int mf = 0; mf < 4; mf++) {
#pragma unroll
                for (int nf = 0; nf < 4; nf++) {
                    const uint32_t b0h = bh[nf >> 1][(nf & 1) * 2];
                    const uint32_t b1h = bh[nf >> 1][(nf & 1) * 2 + 1];
                    const uint32_t b0l = bl[nf >> 1][(nf & 1) * 2];
                    const uint32_t b1l = bl[nf >> 1][(nf & 1) * 2 + 1];
                    MMA_BF16(acc[mf][nf], ah[mf], b0h, b1h);
                    MMA_BF16(acc[mf][nf], ah[mf], b0l, b1l);
                    MMA_BF16(acc[mf][nf], al[mf], b0h, b1h);
                }
            }
        }

        if (more) {
            char* st = smem + ((c + 1) & 1) * STAGE_B;
#pragma unroll
            for (int j = 0; j < 2; j++) {
                const uint32_t o = soff0 + j * 16;
                *reinterpret_cast<uint4*>(st + T_AH + o) = rAh[j];
                *reinterpret_cast<uint4*>(st + T_AL + o) = rAl[j];
                *reinterpret_cast<uint4*>(st + T_BH + o) = rWh[j];
                *reinterpret_cast<uint4*>(st + T_BL + o) = rWl[j];
            }
        }
        __syncthreads();
    }

    const int g  = lane >> 2;
    const int t2 = (lane & 3) * 2;
    const float sc = (SCALE_Q8 && bx < 8) ? 0.125f : 1.0f;
#pragma unroll
    for (int mf = 0; mf < 4; mf++) {
#pragma unroll
        for (int nf = 0; nf < 4; nf++) {
            const int m = bm + wm + mf * 16 + g;
            const int n = cn + wn + nf * 8 + t2;
            float2 v0, v1;
            v0.x = acc[mf][nf][0]; v0.y = acc[mf][nf][1];
            v1.x = acc[mf][nf][2]; v1.y = acc[mf][nf][3];
            if (OUT_BF16) {
                v0.x *= sc; v0.y *= sc; v1.x *= sc; v1.y *= sc;
                uint32_t l0_, l1_;
                uint32_t h0_ = hi_lo_pack(v0.x, v0.y, l0_);
                uint32_t h1_ = hi_lo_pack(v1.x, v1.y, l1_);
                *reinterpret_cast<uint32_t*>(&Ch[(size_t)m * ldc + n]) = h0_;
                *reinterpret_cast<uint32_t*>(&Cl[(size_t)m * ldc + n]) = l0_;
                *reinterpret_cast<uint32_t*>(&Ch[(size_t)(m + 8) * ldc + n]) = h1_;
                *reinterpret_cast<uint32_t*>(&Cl[(size_t)(m + 8) * ldc + n]) = l1_;
            } else {
                if (HAS_BIAS) {
                    const float2 bv = *reinterpret_cast<const float2*>(&bias[n]);
                    v0.x += bv.x; v0.y += bv.y;
                    v1.x += bv.x; v1.y += bv.y;
                }
                *reinterpret_cast<float2*>(&C[(size_t)m * ldc + n]) = v0;
                *reinterpret_cast<float2*>(&C[(size_t)(m + 8) * ldc + n]) = v1;
            }
        }
    }
}

// ===========================================================================
// Tensor-core causal flash attention — pre-split bf16 hi/lo inputs/outputs.
// Same fragment machinery as R7 (verified).
// ===========================================================================
#define FROWB 144
#define SQH   0
#define SQL   18432
#define SKH   0
#define SKL   9216
#define SVH   18432
#define SVL   27648
#define FLASH_SMEM_BYTES 36864

__global__ void __launch_bounds__(256) flash_mma(
    const __nv_bfloat16* __restrict__ qkvh,
    const __nv_bfloat16* __restrict__ qkvl,
    __nv_bfloat16* __restrict__ atth,
    __nv_bfloat16* __restrict__ attl)
{
    extern __shared__ __align__(128) char smem[];
    const uint32_t sbase = smem_u32(smem);
    const int tid  = threadIdx.x;
    const int lane = tid & 31;
    const int w    = tid >> 5;
    const int qt   = (gridDim.x - 1) - blockIdx.x;
    const int h    = blockIdx.y;
    const int b    = blockIdx.z;

    const size_t head_base = (size_t)b * S_LEN * QKV_LD + (size_t)h * HD;

    // ---- Stage Q (already scaled) hi/lo : plain uint4 copies ----
    {
        const int r = tid >> 1;
        const int g0 = (tid & 1) * 4;
        const __nv_bfloat16* qrh = qkvh + head_base + (size_t)(qt * 128 + r) * QKV_LD;
        const __nv_bfloat16* qrl = qkvl + head_base + (size_t)(qt * 128 + r) * QKV_LD;
#pragma unroll
        for (int t = 0; t < 4; t++) {
            const int gg = g0 + t;
            const uint32_t off = (uint32_t)r * FROWB + gg * 16;
            *reinterpret_cast<uint4*>(smem + SQH + off) =
                *reinterpret_cast<const uint4*>(qrh + gg * 8);
            *reinterpret_cast<uint4*>(smem + SQL + off) =
                *reinterpret_cast<const uint4*>(qrl + gg * 8);
        }
    }
    __syncthreads();

    uint32_t qh[4][4], ql[4][4];
    {
        const uint32_t a_off = (uint32_t)(w * 16 + (lane & 15)) * FROWB
                               + ((lane >> 4) * 8) * 2;
#pragma unroll
        for (int ks = 0; ks < 4; ks++) {
            LDM4(qh[ks], sbase + SQH + a_off + ks * 32);
            LDM4(ql[ks], sbase + SQL + a_off + ks * 32);
        }
    }
    __syncthreads();

    float o[8][4];
#pragma unroll
    for (int nf = 0; nf < 8; nf++)
#pragma unroll
        for (int r = 0; r < 4; r++) o[nf][r] = 0.f;
    float m0 = -1e30f, m1 = -1e30f, l0 = 0.f, l1 = 0.f;

    const int g  = lane >> 2;
    const int t2 = (lane & 3) * 2;
    const int wrow = qt * 128 + w * 16;
    const int row0 = wrow + g;
    const int row1 = row0 + 8;

    const uint32_t kb_off = (uint32_t)((lane >> 4) * 8 + (lane & 7)) * FROWB
                            + (((lane >> 3) & 1) * 8) * 2;
    const uint32_t vt_row = (uint32_t)(lane & 15) * FROWB + ((lane >> 4) * 8) * 2;

    const int kt_end = 2 * qt + 1;
    for (int kt = 0; kt <= kt_end; kt++) {
        // ---- K,V tile hi/lo: plain uint4 copies ----
        {
            const int r = tid >> 2;
            const int g0 = (tid & 3) * 2;
            const size_t rowb = head_base + (size_t)(kt * 64 + r) * QKV_LD;
#pragma unroll
            for (int t = 0; t < 2; t++) {
                const int gg = g0 + t;
                const uint32_t off = (uint32_t)r * FROWB + gg * 16;
                *reinterpret_cast<uint4*>(smem + SKH + off) =
                    *reinterpret_cast<const uint4*>(qkvh + rowb + D_MODEL + gg * 8);
                *reinterpret_cast<uint4*>(smem + SKL + off) =
                    *reinterpret_cast<const uint4*>(qkvl + rowb + D_MODEL + gg * 8);
                *reinterpret_cast<uint4*>(smem + SVH + off) =
                    *reinterpret_cast<const uint4*>(qkvh + rowb + 2 * D_MODEL + gg * 8);
                *reinterpret_cast<uint4*>(smem + SVL + off) =
                    *reinterpret_cast<const uint4*>(qkvl + rowb + 2 * D_MODEL + gg * 8);
            }
        }
        __syncthreads();

        const bool active = (kt * 64 <= wrow + 15);
        if (active) {
            float s[8][4];
#pragma unroll
            for (int nf = 0; nf < 8; nf++)
#pragma unroll
                for (int r = 0; r < 4; r++) s[nf][r] = 0.f;

#pragma unroll
            for (int ks = 0; ks < 4; ks++) {
#pragma unroll
                for (int p = 0; p < 4; p++) {
                    uint32_t kh[4], kl[4];
                    LDM4(kh, sbase + SKH + kb_off + p * (16 * FROWB) + ks * 32);
                    LDM4(kl, sbase + SKL + kb_off + p * (16 * FROWB) + ks * 32);
                    MMA_BF16(s[2 * p],     qh[ks], kh[0], kh[1]);
                    MMA_BF16(s[2 * p],     qh[ks], kl[0], kl[1]);
                    MMA_BF16(s[2 * p],     ql[ks], kh[0], kh[1]);
                    MMA_BF16(s[2 * p + 1], qh[ks], kh[2], kh[3]);
                    MMA_BF16(s[2 * p + 1], qh[ks], kl[2], kl[3]);
                    MMA_BF16(s[2 * p + 1], ql[ks], kh[2], kh[3]);
                }
            }

            if (kt * 64 + 63 > wrow) {
#pragma unroll
                for (int nf = 0; nf < 8; nf++) {
                    const int c0 = kt * 64 + nf * 8 + t2;
                    if (c0     > row0) s[nf][0] = -1e30f;
                    if (c0 + 1 > row0) s[nf][1] = -1e30f;
                    if (c0     > row1) s[nf][2] = -1e30f;
                    if (c0 + 1 > row1) s[nf][3] = -1e30f;
                }
            }

            float mx0 = s[0][0], mx1 = s[0][2];
#pragma unroll
            for (int nf = 0; nf < 8; nf++) {
                mx0 = fmaxf(mx0, fmaxf(s[nf][0], s[nf][1]));
                mx1 = fmaxf(mx1, fmaxf(s[nf][2], s[nf][3]));
            }
            mx0 = fmaxf(mx0, __shfl_xor_sync(0xffffffffu, mx0, 1));
            mx0 = fmaxf(mx0, __shfl_xor_sync(0xffffffffu, mx0, 2));
            mx1 = fmaxf(mx1, __shfl_xor_sync(0xffffffffu, mx1, 1));
            mx1 = fmaxf(mx1, __shfl_xor_sync(0xffffffffu, mx1, 2));

            const float nm0 = fmaxf(m0, mx0), nm1 = fmaxf(m1, mx1);
            const float a0 = __expf(m0 - nm0), a1 = __expf(m1 - nm1);
            m0 = nm0; m1 = nm1;

            float sum0 = 0.f, sum1 = 0.f;
#pragma unroll
            for (int nf = 0; nf < 8; nf++) {
                s[nf][0] = __expf(s[nf][0] - nm0);
                s[nf][1] = __expf(s[nf][1] - nm0);
                s[nf][2] = __expf(s[nf][2] - nm1);
                s[nf][3] = __expf(s[nf][3] - nm1);
                sum0 += s[nf][0] + s[nf][1];
                sum1 += s[nf][2] + s[nf][3];
            }
            sum0 += __shfl_xor_sync(0xffffffffu, sum0, 1);
            sum0 += __shfl_xor_sync(0xffffffffu, sum0, 2);
            sum1 += __shfl_xor_sync(0xffffffffu, sum1, 1);
            sum1 += __shfl_xor_sync(0xffffffffu, sum1, 2);
            l0 = l0 * a0 + sum0;
            l1 = l1 * a1 + sum1;

#pragma unroll
            for (int nf = 0; nf < 8; nf++) {
                o[nf][0] *= a0; o[nf][1] *= a0;
                o[nf][2] *= a1; o[nf][3] *= a1;
            }

#pragma unroll
            for (int j = 0; j < 4; j++) {
                uint32_t ph[4], pl[4];
                ph[0] = hi_lo_pack(s[2 * j][0],     s[2 * j][1],     pl[0]);
                ph[1] = hi_lo_pack(s[2 * j][2],     s[2 * j][3],     pl[1]);
                ph[2] = hi_lo_pack(s[2 * j + 1][0], s[2 * j + 1][1], pl[2]);
                ph[3] = hi_lo_pack(s[2 * j + 1][2], s[2 * j + 1][3], pl[3]);

                const uint32_t vbase = (uint32_t)(j * 16) * FROWB + vt_row;
#pragma unroll
                for (int hg = 0; hg < 4; hg++) {
                    uint32_t vh[4], vl[4];
                    LDM4T(vh, sbase + SVH + vbase + hg * 32);
                    LDM4T(vl, sbase + SVL + vbase + hg * 32);
                    MMA_BF16(o[2 * hg],     ph, vh[0], vh[1]);
                    MMA_BF16(o[2 * hg],     ph, vl[0], vl[1]);
                    MMA_BF16(o[2 * hg],     pl, vh[0], vh[1]);
                    MMA_BF16(o[2 * hg + 1], ph, vh[2], vh[3]);
                    MMA_BF16(o[2 * hg + 1], ph, vl[2], vl[3]);
                    MMA_BF16(o[2 * hg + 1], pl, vh[2], vh[3]);
                }
            }
        }
        __syncthreads();
    }

    // ---- Normalize and write attn as bf16 hi/lo ----
    const float inv0 = 1.f / l0, inv1 = 1.f / l1;
    const size_t ob = ((size_t)b * S_LEN + qt * 128 + w * 16) * D_MODEL
                      + (size_t)h * HD;
#pragma unroll
    for (int nf = 0; nf < 8; nf++) {
        const int c = nf * 8 + t2;
        uint32_t lo0, lo1;
        uint32_t hi0 = hi_lo_pack(o[nf][0] * inv0, o[nf][1] * inv0, lo0);
        uint32_t hi1 = hi_lo_pack(o[nf][2] * inv1, o[nf][3] * inv1, lo1);
        *reinterpret_cast<uint32_t*>(&atth[ob + (size_t)g * D_MODEL + c]) = hi0;
        *reinterpret_cast<uint32_t*>(&attl[ob + (size_t)g * D_MODEL + c]) = lo0;
        *reinterpret_cast<uint32_t*>(&atth[ob + (size_t)(g + 8) * D_MODEL + c]) = hi1;
        *reinterpret_cast<uint32_t*>(&attl[ob + (size_t)(g + 8) * D_MODEL + c]) = lo1;
    }
}

// ---------------------------------------------------------------------------
extern "C" void kernel_launch(void* const* d_in, const int* in_sizes, int n_in,
                              void* d_out, int out_size)
{
    const float* x    = (const float*)d_in[0];
    const float* wq   = (const float*)d_in[1];
    const float* wk   = (const float*)d_in[2];
    const float* wv   = (const float*)d_in[3];
    const float* wo_w = (const float*)d_in[4];
    const float* wo_b = (const float*)d_in[5];
    float* out = (float*)d_out;

    __nv_bfloat16 *xh, *xl, *wh, *wl, *woh, *wol, *qkvh, *qkvl, *atth, *attl;
    cudaGetSymbolAddress((void**)&xh,   g_xh);
    cudaGetSymbolAddress((void**)&xl,   g_xl);
    cudaGetSymbolAddress((void**)&wh,   g_wh);
    cudaGetSymbolAddress((void**)&wl,   g_wl);
    cudaGetSymbolAddress((void**)&woh,  g_woh);
    cudaGetSymbolAddress((void**)&wol,  g_wol);
    cudaGetSymbolAddress((void**)&qkvh, g_qkvh);
    cudaGetSymbolAddress((void**)&qkvl, g_qkvl);
    cudaGetSymbolAddress((void**)&atth, g_atth);
    cudaGetSymbolAddress((void**)&attl, g_attl);

    static bool attr_done = false;
    if (!attr_done) {
        cudaFuncSetAttribute((const void*)mma_gemm<false, true, true>,
                             cudaFuncAttributeMaxDynamicSharedMemorySize,
                             GEMM_SMEM_BYTES);
        cudaFuncSetAttribute((const void*)mma_gemm<true, false, false>,
                             cudaFuncAttributeMaxDynamicSharedMemorySize,
                             GEMM_SMEM_BYTES);
        attr_done = true;
    }

    const int DSQ = D_MODEL * D_MODEL;          // 1M elems
    // One-shot conversions
    cvt_hl<<<(M_ROWS * D_MODEL / 4 + 255) / 256, 256>>>(x, xh, xl, M_ROWS * D_MODEL / 4);
    cvt_hl<<<(DSQ / 4 + 255) / 256, 256>>>(wq,   wh,            wl,            DSQ / 4);
    cvt_hl<<<(DSQ / 4 + 255) / 256, 256>>>(wk,   wh + DSQ,      wl + DSQ,      DSQ / 4);
    cvt_hl<<<(DSQ / 4 + 255) / 256, 256>>>(wv,   wh + 2 * DSQ,  wl + 2 * DSQ,  DSQ / 4);
    cvt_hl<<<(DSQ / 4 + 255) / 256, 256>>>(wo_w, woh,           wol,           DSQ / 4);

    // Fused QKV projection -> bf16 hi/lo (Q pre-scaled x0.125)
    const dim3 qkv_grid(24, M_ROWS / 128);
    mma_gemm<false, true, true><<<qkv_grid, 256, GEMM_SMEM_BYTES>>>(
        xh, xl, wh, wl, nullptr, nullptr, qkvh, qkvl, D_MODEL, QKV_LD);

    // Tensor-core causal flash attention -> attn bf16 hi/lo
    const dim3 flash_grid(S_LEN / 128, NHEAD, B_SZ);
    flash_mma<<<flash_grid, 256, FLASH_SMEM_BYTES>>>(qkvh, qkvl, atth, attl);

    // Output projection (f32 out, bias)
    const dim3 o_grid(8, M_ROWS / 128);
    mma_gemm<true, false, false><<<o_grid, 256, GEMM_SMEM_BYTES>>>(
        atth, attl, woh, wol, wo_b, out, nullptr, nullptr, D_MODEL, D_MODEL);
}

// round 9
// speedup vs baseline: 2.4404x; 1.0554x over previous
#include <cuda_runtime.h>
#include <cuda_bf16.h>
#include <cstdint>

#define B_SZ    2
#define S_LEN   2048
#define D_MODEL 1024
#define NHEAD   16
#define HD      64
#define M_ROWS  (B_SZ * S_LEN)      // 4096
#define QKV_LD  (3 * D_MODEL)       // 3072

// bf16 hi/lo scratch (device globals)
__device__ __nv_bfloat16 g_xh [(size_t)M_ROWS * D_MODEL];
__device__ __nv_bfloat16 g_xl [(size_t)M_ROWS * D_MODEL];
__device__ __nv_bfloat16 g_wh [(size_t)3 * D_MODEL * D_MODEL];  // wq|wk|wv
__device__ __nv_bfloat16 g_wl [(size_t)3 * D_MODEL * D_MODEL];
__device__ __nv_bfloat16 g_woh[(size_t)D_MODEL * D_MODEL];
__device__ __nv_bfloat16 g_wol[(size_t)D_MODEL * D_MODEL];
__device__ __nv_bfloat16 g_qkvh[(size_t)M_ROWS * QKV_LD];       // Q(x0.125)|K|V
__device__ __nv_bfloat16 g_qkvl[(size_t)M_ROWS * QKV_LD];
__device__ __nv_bfloat16 g_atth[(size_t)M_ROWS * D_MODEL];
__device__ __nv_bfloat16 g_attl[(size_t)M_ROWS * D_MODEL];

__device__ __forceinline__ uint32_t smem_u32(const void* p) {
    uint32_t a;
    asm("{ .reg .u64 t; cvta.to.shared.u64 t, %1; cvt.u32.u64 %0, t; }"
        : "=r"(a) : "l"(p));
    return a;
}

#define LDM4(r, addr) \
    asm volatile("ldmatrix.sync.aligned.m8n8.x4.shared.b16 {%0,%1,%2,%3}, [%4];" \
        : "=r"((r)[0]), "=r"((r)[1]), "=r"((r)[2]), "=r"((r)[3]) : "r"(addr))

#define LDM4T(r, addr) \
    asm volatile("ldmatrix.sync.aligned.m8n8.x4.trans.shared.b16 {%0,%1,%2,%3}, [%4];" \
        : "=r"((r)[0]), "=r"((r)[1]), "=r"((r)[2]), "=r"((r)[3]) : "r"(addr))

#define MMA_BF16(d, a, b0, b1) \
    asm volatile("mma.sync.aligned.m16n8k16.row.col.f32.bf16.bf16.f32 " \
        "{%0,%1,%2,%3}, {%4,%5,%6,%7}, {%8,%9}, {%0,%1,%2,%3};" \
        : "+f"((d)[0]), "+f"((d)[1]), "+f"((d)[2]), "+f"((d)[3]) \
        : "r"((a)[0]), "r"((a)[1]), "r"((a)[2]), "r"((a)[3]), "r"(b0), "r"(b1))

#define CP16(dst, src) \
    asm volatile("cp.async.cg.shared.global [%0], [%1], 16;" \
        :: "r"(dst), "l"(src) : "memory")
#define CP_COMMIT() asm volatile("cp.async.commit_group;" ::: "memory")
#define CP_WAIT0()  asm volatile("cp.async.wait_group 0;" ::: "memory")

__device__ __forceinline__ uint32_t pack2(__nv_bfloat16 a, __nv_bfloat16 b) {
    return (uint32_t)__bfloat16_as_ushort(a) |
           ((uint32_t)__bfloat16_as_ushort(b) << 16);
}

__device__ __forceinline__ void cvt4(float4 v, uint2& h, uint2& l) {
    __nv_bfloat16 h0 = __float2bfloat16_rn(v.x);
    __nv_bfloat16 h1 = __float2bfloat16_rn(v.y);
    __nv_bfloat16 h2 = __float2bfloat16_rn(v.z);
    __nv_bfloat16 h3 = __float2bfloat16_rn(v.w);
    __nv_bfloat16 l0 = __float2bfloat16_rn(v.x - __bfloat162float(h0));
    __nv_bfloat16 l1 = __float2bfloat16_rn(v.y - __bfloat162float(h1));
    __nv_bfloat16 l2 = __float2bfloat16_rn(v.z - __bfloat162float(h2));
    __nv_bfloat16 l3 = __float2bfloat16_rn(v.w - __bfloat162float(h3));
    h.x = pack2(h0, h1); h.y = pack2(h2, h3);
    l.x = pack2(l0, l1); l.y = pack2(l2, l3);
}

__device__ __forceinline__ uint32_t hi_lo_pack(float a, float b, uint32_t& lo) {
    __nv_bfloat16 ha = __float2bfloat16_rn(a);
    __nv_bfloat16 hb = __float2bfloat16_rn(b);
    lo = pack2(__float2bfloat16_rn(a - __bfloat162float(ha)),
               __float2bfloat16_rn(b - __bfloat162float(hb)));
    return pack2(ha, hb);
}

__global__ void cvt_hl(const float* __restrict__ src,
                       __nv_bfloat16* __restrict__ h,
                       __nv_bfloat16* __restrict__ l, int n4)
{
    const int i = blockIdx.x * blockDim.x + threadIdx.x;
    if (i < n4) {
        float4 v = reinterpret_cast<const float4*>(src)[i];
        uint2 hh, ll;
        cvt4(v, hh, ll);
        reinterpret_cast<uint2*>(h)[i] = hh;
        reinterpret_cast<uint2*>(l)[i] = ll;
    }
}

// ===========================================================================
// mma.sync bf16x3 GEMM, pre-split inputs, cp.async 2-stage pipeline.
// CTA 128x128, BK=32, 8 warps, warp tile 64x32, 2 CTAs/SM.
// ===========================================================================
#define ROWB    80
#define T_AH    0
#define T_AL    10240
#define T_BH    20480
#define T_BL    30720
#define STAGE_B 40960
#define GEMM_SMEM_BYTES (2 * STAGE_B)

template <bool HAS_BIAS, bool OUT_BF16, bool SCALE_Q8>
__global__ void __launch_bounds__(256, 2) mma_gemm(
    const __nv_bfloat16* __restrict__ Ah, const __nv_bfloat16* __restrict__ Al,
    const __nv_bfloat16* __restrict__ Wh, const __nv_bfloat16* __restrict__ Wl,
    const float* __restrict__ bias,
    float* __restrict__ C,
    __nv_bfloat16* __restrict__ Ch, __nv_bfloat16* __restrict__ Cl,
    int K, int ldc)
{
    extern __shared__ __align__(128) char smem[];
    const uint32_t sbase = smem_u32(smem);
    const int tid  = threadIdx.x;
    const int lane = tid & 31;
    const int bx   = blockIdx.x;
    const int bm   = blockIdx.y * 128;
    const int bn   = (bx & 7) * 128;
    const int cn   = (bx >> 3) * D_MODEL + bn;
    const size_t woff = (size_t)(bx >> 3) * D_MODEL * D_MODEL;

    const int wm = (tid >> 7) * 64;
    const int wn = ((tid >> 5) & 3) * 32;

    const uint32_t a_off = (uint32_t)(wm + (lane & 15)) * ROWB + ((lane >> 4) * 8) * 2;
    const uint32_t b_off = (uint32_t)(wn + (lane >> 4) * 8 + (lane & 7)) * ROWB
                           + (((lane >> 3) & 1) * 8) * 2;

    // Loader: thread -> row lr, two 16B quarters
    const int lr = tid >> 1;
    const int lq = (tid & 1) * 2;
    const __nv_bfloat16* pAh = Ah + (size_t)(bm + lr) * K;
    const __nv_bfloat16* pAl = Al + (size_t)(bm + lr) * K;
    const __nv_bfloat16* pWh = Wh + woff + (size_t)(bn + lr) * K;
    const __nv_bfloat16* pWl = Wl + woff + (size_t)(bn + lr) * K;
    const uint32_t soff0 = (uint32_t)lr * ROWB + lq * 16;

    float acc[4][4][4];
#pragma unroll
    for (int i = 0; i < 4; i++)
#pragma unroll
        for (int j = 0; j < 4; j++)
#pragma unroll
            for (int r = 0; r < 4; r++) acc[i][j][r] = 0.f;

    const int nch = K / 32;

    // prologue: chunk 0 -> stage 0
    {
        const uint32_t sb = sbase;
#pragma unroll
        for (int j = 0; j < 2; j++) {
            const int eo = (lq + j) * 8;
            const uint32_t o = soff0 + j * 16;
            CP16(sb + T_AH + o, pAh + eo);
            CP16(sb + T_AL + o, pAl + eo);
            CP16(sb + T_BH + o, pWh + eo);
            CP16(sb + T_BL + o, pWl + eo);
        }
        CP_COMMIT();
    }

    for (int c = 0; c < nch; c++) {
        CP_WAIT0();
        __syncthreads();

        if (c + 1 < nch) {
            const uint32_t sb = sbase + ((c + 1) & 1) * STAGE_B;
            const int k0 = (c + 1) * 32;
#pragma unroll
            for (int j = 0; j < 2; j++) {
                const int eo = k0 + (lq + j) * 8;
                const uint32_t o = soff0 + j * 16;
                CP16(sb + T_AH + o, pAh + eo);
                CP16(sb + T_AL + o, pAl + eo);
                CP16(sb + T_BH + o, pWh + eo);
                CP16(sb + T_BL + o, pWl + eo);
            }
            CP_COMMIT();
        }

        const uint32_t stb = sbase + (c & 1) * STAGE_B;
#pragma unroll
        for (int kk = 0; kk < 2; kk++) {
            const uint32_t ko = kk * 32;
            uint32_t ah[4][4], al[4][4];
#pragma unroll
            for (int mf = 0; mf < 4; mf++) {
                LDM4(ah[mf], stb + T_AH + a_off + mf * (16 * ROWB) + ko);
                LDM4(al[mf], stb + T_AL + a_off + mf * (16 * ROWB) + ko);
            }
            uint32_t bh[2][4], bl[2][4];
#pragma unroll
            for (int p = 0; p < 2; p++) {
                LDM4(bh[p], stb + T_BH + b_off + p * (16 * ROWB) + ko);
                LDM4(bl[p], stb + T_BL + b_off + p * (16 * ROWB) + ko);
            }
#pragma unroll
            for (int mf = 0; mf < 4; mf++) {
#pragma unroll
                for (int nf = 0; nf < 4; nf++) {
                    const uint32_t b0h = bh[nf >> 1][(nf & 1) * 2];
                    const uint32_t b1h = bh[nf >> 1][(nf & 1) * 2 + 1];
                    const uint32_t b0l = bl[nf >> 1][(nf & 1) * 2];
                    const uint32_t b1l = bl[nf >> 1][(nf & 1) * 2 + 1];
                    MMA_BF16(acc[mf][nf], ah[mf], b0h, b1h);
                    MMA_BF16(acc[mf][nf], ah[mf], b0l, b1l);
                    MMA_BF16(acc[mf][nf], al[mf], b0h, b1h);
                }
            }
        }
    }

    const int g  = lane >> 2;
    const int t2 = (lane & 3) * 2;
    const float sc = (SCALE_Q8 && bx < 8) ? 0.125f : 1.0f;
#pragma unroll
    for (int mf = 0; mf < 4; mf++) {
#pragma unroll
        for (int nf = 0; nf < 4; nf++) {
            const int m = bm + wm + mf * 16 + g;
            const int n = cn + wn + nf * 8 + t2;
            float2 v0, v1;
            v0.x = acc[mf][nf][0]; v0.y = acc[mf][nf][1];
            v1.x = acc[mf][nf][2]; v1.y = acc[mf][nf][3];
            if (OUT_BF16) {
                v0.x *= sc; v0.y *= sc; v1.x *= sc; v1.y *= sc;
                uint32_t l0_, l1_;
                uint32_t h0_ = hi_lo_pack(v0.x, v0.y, l0_);
                uint32_t h1_ = hi_lo_pack(v1.x, v1.y, l1_);
                *reinterpret_cast<uint32_t*>(&Ch[(size_t)m * ldc + n]) = h0_;
                *reinterpret_cast<uint32_t*>(&Cl[(size_t)m * ldc + n]) = l0_;
                *reinterpret_cast<uint32_t*>(&Ch[(size_t)(m + 8) * ldc + n]) = h1_;
                *reinterpret_cast<uint32_t*>(&Cl[(size_t)(m + 8) * ldc + n]) = l1_;
            } else {
                if (HAS_BIAS) {
                    const float2 bv = *reinterpret_cast<const float2*>(&bias[n]);
                    v0.x += bv.x; v0.y += bv.y;
                    v1.x += bv.x; v1.y += bv.y;
                }
                *reinterpret_cast<float2*>(&C[(size_t)m * ldc + n]) = v0;
                *reinterpret_cast<float2*>(&C[(size_t)(m + 8) * ldc + n]) = v1;
            }
        }
    }
}

// ===========================================================================
// Tensor-core causal flash attention, cp.async double-buffered K/V stages.
// ===========================================================================
#define FROWB 144
#define KV_KH 0
#define KV_KL 9216
#define KV_VH 18432
#define KV_VL 27648
#define KV_STAGE 36864
#define SQH   0
#define SQL   18432
#define FLASH_SMEM_BYTES (2 * KV_STAGE)   // 73728

__global__ void __launch_bounds__(256) flash_mma(
    const __nv_bfloat16* __restrict__ qkvh,
    const __nv_bfloat16* __restrict__ qkvl,
    __nv_bfloat16* __restrict__ atth,
    __nv_bfloat16* __restrict__ attl)
{
    extern __shared__ __align__(128) char smem[];
    const uint32_t sbase = smem_u32(smem);
    const int tid  = threadIdx.x;
    const int lane = tid & 31;
    const int w    = tid >> 5;
    const int qt   = (gridDim.x - 1) - blockIdx.x;
    const int h    = blockIdx.y;
    const int b    = blockIdx.z;

    const size_t head_base = (size_t)b * S_LEN * QKV_LD + (size_t)h * HD;

    // ---- Stage Q hi/lo into stage0 area, load A-fragments ----
    {
        const int r = tid >> 1;
        const int g0 = (tid & 1) * 4;
        const __nv_bfloat16* qrh = qkvh + head_base + (size_t)(qt * 128 + r) * QKV_LD;
        const __nv_bfloat16* qrl = qkvl + head_base + (size_t)(qt * 128 + r) * QKV_LD;
#pragma unroll
        for (int t = 0; t < 4; t++) {
            const int gg = g0 + t;
            const uint32_t off = (uint32_t)r * FROWB + gg * 16;
            *reinterpret_cast<uint4*>(smem + SQH + off) =
                *reinterpret_cast<const uint4*>(qrh + gg * 8);
            *reinterpret_cast<uint4*>(smem + SQL + off) =
                *reinterpret_cast<const uint4*>(qrl + gg * 8);
        }
    }
    __syncthreads();

    uint32_t qh[4][4], ql[4][4];
    {
        const uint32_t a_off = (uint32_t)(w * 16 + (lane & 15)) * FROWB
                               + ((lane >> 4) * 8) * 2;
#pragma unroll
        for (int ks = 0; ks < 4; ks++) {
            LDM4(qh[ks], sbase + SQH + a_off + ks * 32);
            LDM4(ql[ks], sbase + SQL + a_off + ks * 32);
        }
    }
    __syncthreads();

    float o[8][4];
#pragma unroll
    for (int nf = 0; nf < 8; nf++)
#pragma unroll
        for (int r = 0; r < 4; r++) o[nf][r] = 0.f;
    float m0 = -1e30f, m1 = -1e30f, l0 = 0.f, l1 = 0.f;

    const int g  = lane >> 2;
    const int t2 = (lane & 3) * 2;
    const int wrow = qt * 128 + w * 16;
    const int row0 = wrow + g;
    const int row1 = row0 + 8;

    const uint32_t kb_off = (uint32_t)((lane >> 4) * 8 + (lane & 7)) * FROWB
                            + (((lane >> 3) & 1) * 8) * 2;
    const uint32_t vt_row = (uint32_t)(lane & 15) * FROWB + ((lane >> 4) * 8) * 2;

    // KV loader mapping
    const int klr = tid >> 2;            // row 0..63
    const int kg0 = (tid & 3) * 2;       // granule base (2 granules)

    const int kt_end = 2 * qt + 1;

    // prologue: kt=0 -> buf 0
    {
        const uint32_t sb = sbase;
        const size_t rowb = head_base + (size_t)klr * QKV_LD;
#pragma unroll
        for (int t = 0; t < 2; t++) {
            const int gg = kg0 + t;
            const uint32_t off = (uint32_t)klr * FROWB + gg * 16;
            CP16(sb + KV_KH + off, qkvh + rowb + D_MODEL + gg * 8);
            CP16(sb + KV_KL + off, qkvl + rowb + D_MODEL + gg * 8);
            CP16(sb + KV_VH + off, qkvh + rowb + 2 * D_MODEL + gg * 8);
            CP16(sb + KV_VL + off, qkvl + rowb + 2 * D_MODEL + gg * 8);
        }
        CP_COMMIT();
    }

    for (int kt = 0; kt <= kt_end; kt++) {
        CP_WAIT0();
        __syncthreads();

        if (kt < kt_end) {
            const uint32_t sb = sbase + ((kt + 1) & 1) * KV_STAGE;
            const size_t rowb = head_base + (size_t)((kt + 1) * 64 + klr) * QKV_LD;
#pragma unroll
            for (int t = 0; t < 2; t++) {
                const int gg = kg0 + t;
                const uint32_t off = (uint32_t)klr * FROWB + gg * 16;
                CP16(sb + KV_KH + off, qkvh + rowb + D_MODEL + gg * 8);
                CP16(sb + KV_KL + off, qkvl + rowb + D_MODEL + gg * 8);
                CP16(sb + KV_VH + off, qkvh + rowb + 2 * D_MODEL + gg * 8);
                CP16(sb + KV_VL + off, qkvl + rowb + 2 * D_MODEL + gg * 8);
            }
            CP_COMMIT();
        }

        const bool active = (kt * 64 <= wrow + 15);
        if (active) {
            const uint32_t stb = sbase + (kt & 1) * KV_STAGE;
            float s[8][4];
#pragma unroll
            for (int nf = 0; nf < 8; nf++)
#pragma unroll
                for (int r = 0; r < 4; r++) s[nf][r] = 0.f;

#pragma unroll
            for (int ks = 0; ks < 4; ks++) {
#pragma unroll
                for (int p = 0; p < 4; p++) {
                    uint32_t kh[4], kl[4];
                    LDM4(kh, stb + KV_KH + kb_off + p * (16 * FROWB) + ks * 32);
                    LDM4(kl, stb + KV_KL + kb_off + p * (16 * FROWB) + ks * 32);
                    MMA_BF16(s[2 * p],     qh[ks], kh[0], kh[1]);
                    MMA_BF16(s[2 * p],     qh[ks], kl[0], kl[1]);
                    MMA_BF16(s[2 * p],     ql[ks], kh[0], kh[1]);
                    MMA_BF16(s[2 * p + 1], qh[ks], kh[2], kh[3]);
                    MMA_BF16(s[2 * p + 1], qh[ks], kl[2], kl[3]);
                    MMA_BF16(s[2 * p + 1], ql[ks], kh[2], kh[3]);
                }
            }

            if (kt * 64 + 63 > wrow) {
#pragma unroll
                for (int nf = 0; nf < 8; nf++) {
                    const int c0 = kt * 64 + nf * 8 + t2;
                    if (c0     > row0) s[nf][0] = -1e30f;
                    if (c0 + 1 > row0) s[nf][1] = -1e30f;
                    if (c0     > row1) s[nf][2] = -1e30f;
                    if (c0 + 1 > row1) s[nf][3] = -1e30f;
                }
            }

            float mx0 = s[0][0], mx1 = s[0][2];
#pragma unroll
            for (int nf = 0; nf < 8; nf++) {
                mx0 = fmaxf(mx0, fmaxf(s[nf][0], s[nf][1]));
                mx1 = fmaxf(mx1, fmaxf(s[nf][2], s[nf][3]));
            }
            mx0 = fmaxf(mx0, __shfl_xor_sync(0xffffffffu, mx0, 1));
            mx0 = fmaxf(mx0, __shfl_xor_sync(0xffffffffu, mx0, 2));
            mx1 = fmaxf(mx1, __shfl_xor_sync(0xffffffffu, mx1, 1));
            mx1 = fmaxf(mx1, __shfl_xor_sync(0xffffffffu, mx1, 2));

            const float nm0 = fmaxf(m0, mx0), nm1 = fmaxf(m1, mx1);
            const float a0 = __expf(m0 - nm0), a1 = __expf(m1 - nm1);
            m0 = nm0; m1 = nm1;

            float sum0 = 0.f, sum1 = 0.f;
#pragma unroll
            for (int nf = 0; nf < 8; nf++) {
                s[nf][0] = __expf(s[nf][0] - nm0);
                s[nf][1] = __expf(s[nf][1] - nm0);
                s[nf][2] = __expf(s[nf][2] - nm1);
                s[nf][3] = __expf(s[nf][3] - nm1);
                sum0 += s[nf][0] + s[nf][1];
                sum1 += s[nf][2] + s[nf][3];
            }
            sum0 += __shfl_xor_sync(0xffffffffu, sum0, 1);
            sum0 += __shfl_xor_sync(0xffffffffu, sum0, 2);
            sum1 += __shfl_xor_sync(0xffffffffu, sum1, 1);
            sum1 += __shfl_xor_sync(0xffffffffu, sum1, 2);
            l0 = l0 * a0 + sum0;
            l1 = l1 * a1 + sum1;

#pragma unroll
            for (int nf = 0; nf < 8; nf++) {
                o[nf][0] *= a0; o[nf][1] *= a0;
                o[nf][2] *= a1; o[nf][3] *= a1;
            }

#pragma unroll
            for (int j = 0; j < 4; j++) {
                uint32_t ph[4], pl[4];
                ph[0] = hi_lo_pack(s[2 * j][0],     s[2 * j][1],     pl[0]);
                ph[1] = hi_lo_pack(s[2 * j][2],     s[2 * j][3],     pl[1]);
                ph[2] = hi_lo_pack(s[2 * j + 1][0], s[2 * j + 1][1], pl[2]);
                ph[3] = hi_lo_pack(s[2 * j + 1][2], s[2 * j + 1][3], pl[3]);

                const uint32_t vbase = (uint32_t)(j * 16) * FROWB + vt_row;
#pragma unroll
                for (int hg = 0; hg < 4; hg++) {
                    uint32_t vh[4], vl[4];
                    LDM4T(vh, stb + KV_VH + vbase + hg * 32);
                    LDM4T(vl, stb + KV_VL + vbase + hg * 32);
                    MMA_BF16(o[2 * hg],     ph, vh[0], vh[1]);
                    MMA_BF16(o[2 * hg],     ph, vl[0], vl[1]);
                    MMA_BF16(o[2 * hg],     pl, vh[0], vh[1]);
                    MMA_BF16(o[2 * hg + 1], ph, vh[2], vh[3]);
                    MMA_BF16(o[2 * hg + 1], ph, vl[2], vl[3]);
                    MMA_BF16(o[2 * hg + 1], pl, vh[2], vh[3]);
                }
            }
        }
    }

    // ---- Normalize and write attn as bf16 hi/lo ----
    const float inv0 = 1.f / l0, inv1 = 1.f / l1;
    const size_t ob = ((size_t)b * S_LEN + qt * 128 + w * 16) * D_MODEL
                      + (size_t)h * HD;
#pragma unroll
    for (int nf = 0; nf < 8; nf++) {
        const int c = nf * 8 + t2;
        uint32_t lo0, lo1;
        uint32_t hi0 = hi_lo_pack(o[nf][0] * inv0, o[nf][1] * inv0, lo0);
        uint32_t hi1 = hi_lo_pack(o[nf][2] * inv1, o[nf][3] * inv1, lo1);
        *reinterpret_cast<uint32_t*>(&atth[ob + (size_t)g * D_MODEL + c]) = hi0;
        *reinterpret_cast<uint32_t*>(&attl[ob + (size_t)g * D_MODEL + c]) = lo0;
        *reinterpret_cast<uint32_t*>(&atth[ob + (size_t)(g + 8) * D_MODEL + c]) = hi1;
        *reinterpret_cast<uint32_t*>(&attl[ob + (size_t)(g + 8) * D_MODEL + c]) = lo1;
    }
}

// ---------------------------------------------------------------------------
extern "C" void kernel_launch(void* const* d_in, const int* in_sizes, int n_in,
                              void* d_out, int out_size)
{
    const float* x    = (const float*)d_in[0];
    const float* wq   = (const float*)d_in[1];
    const float* wk   = (const float*)d_in[2];
    const float* wv   = (const float*)d_in[3];
    const float* wo_w = (const float*)d_in[4];
    const float* wo_b = (const float*)d_in[5];
    float* out = (float*)d_out;

    __nv_bfloat16 *xh, *xl, *wh, *wl, *woh, *wol, *qkvh, *qkvl, *atth, *attl;
    cudaGetSymbolAddress((void**)&xh,   g_xh);
    cudaGetSymbolAddress((void**)&xl,   g_xl);
    cudaGetSymbolAddress((void**)&wh,   g_wh);
    cudaGetSymbolAddress((void**)&wl,   g_wl);
    cudaGetSymbolAddress((void**)&woh,  g_woh);
    cudaGetSymbolAddress((void**)&wol,  g_wol);
    cudaGetSymbolAddress((void**)&qkvh, g_qkvh);
    cudaGetSymbolAddress((void**)&qkvl, g_qkvl);
    cudaGetSymbolAddress((void**)&atth, g_atth);
    cudaGetSymbolAddress((void**)&attl, g_attl);

    static bool attr_done = false;
    if (!attr_done) {
        cudaFuncSetAttribute((const void*)mma_gemm<false, true, true>,
                             cudaFuncAttributeMaxDynamicSharedMemorySize,
                             GEMM_SMEM_BYTES);
        cudaFuncSetAttribute((const void*)mma_gemm<true, false, false>,
                             cudaFuncAttributeMaxDynamicSharedMemorySize,
                             GEMM_SMEM_BYTES);
        cudaFuncSetAttribute((const void*)flash_mma,
                             cudaFuncAttributeMaxDynamicSharedMemorySize,
                             FLASH_SMEM_BYTES);
        attr_done = true;
    }

    const int DSQ = D_MODEL * D_MODEL;
    cvt_hl<<<(M_ROWS * D_MODEL / 4 + 255) / 256, 256>>>(x, xh, xl, M_ROWS * D_MODEL / 4);
    cvt_hl<<<(DSQ / 4 + 255) / 256, 256>>>(wq,   wh,            wl,            DSQ / 4);
    cvt_hl<<<(DSQ / 4 + 255) / 256, 256>>>(wk,   wh + DSQ,      wl + DSQ,      DSQ / 4);
    cvt_hl<<<(DSQ / 4 + 255) / 256, 256>>>(wv,   wh + 2 * DSQ,  wl + 2 * DSQ,  DSQ / 4);
    cvt_hl<<<(DSQ / 4 + 255) / 256, 256>>>(wo_w, woh,           wol,           DSQ / 4);

    const dim3 qkv_grid(24, M_ROWS / 128);
    mma_gemm<false, true, true><<<qkv_grid, 256, GEMM_SMEM_BYTES>>>(
        xh, xl, wh, wl, nullptr, nullptr, qkvh, qkvl, D_MODEL, QKV_LD);

    const dim3 flash_grid(S_LEN / 128, NHEAD, B_SZ);
    flash_mma<<<flash_grid, 256, FLASH_SMEM_BYTES>>>(qkvh, qkvl, atth, attl);

    const dim3 o_grid(8, M_ROWS / 128);
    mma_gemm<true, false, false><<<o_grid, 256, GEMM_SMEM_BYTES>>>(
        atth, attl, woh, wol, wo_b, out, nullptr, nullptr, D_MODEL, D_MODEL);
}

// round 10
// speedup vs baseline: 2.5588x; 1.0485x over previous
#include <cuda_runtime.h>
#include <cuda_bf16.h>
#include <cstdint>

#define B_SZ    2
#define S_LEN   2048
#define D_MODEL 1024
#define NHEAD   16
#define HD      64
#define M_ROWS  (B_SZ * S_LEN)      // 4096
#define QKV_LD  (3 * D_MODEL)       // 3072
#define DSQ     (D_MODEL * D_MODEL) // 1048576

// bf16 hi/lo scratch (device globals)
__device__ __nv_bfloat16 g_xh [(size_t)M_ROWS * D_MODEL];
__device__ __nv_bfloat16 g_xl [(size_t)M_ROWS * D_MODEL];
__device__ __nv_bfloat16 g_wh [(size_t)3 * DSQ];               // wq|wk|wv
__device__ __nv_bfloat16 g_wl [(size_t)3 * DSQ];
__device__ __nv_bfloat16 g_woh[(size_t)DSQ];
__device__ __nv_bfloat16 g_wol[(size_t)DSQ];
__device__ __nv_bfloat16 g_qkvh[(size_t)M_ROWS * QKV_LD];      // Q(x0.125)|K|V
__device__ __nv_bfloat16 g_qkvl[(size_t)M_ROWS * QKV_LD];
__device__ __nv_bfloat16 g_atth[(size_t)M_ROWS * D_MODEL];
__device__ __nv_bfloat16 g_attl[(size_t)M_ROWS * D_MODEL];

__device__ __forceinline__ uint32_t smem_u32(const void* p) {
    uint32_t a;
    asm("{ .reg .u64 t; cvta.to.shared.u64 t, %1; cvt.u32.u64 %0, t; }"
        : "=r"(a) : "l"(p));
    return a;
}

#define LDM4(r, addr) \
    asm volatile("ldmatrix.sync.aligned.m8n8.x4.shared.b16 {%0,%1,%2,%3}, [%4];" \
        : "=r"((r)[0]), "=r"((r)[1]), "=r"((r)[2]), "=r"((r)[3]) : "r"(addr))

#define LDM4T(r, addr) \
    asm volatile("ldmatrix.sync.aligned.m8n8.x4.trans.shared.b16 {%0,%1,%2,%3}, [%4];" \
        : "=r"((r)[0]), "=r"((r)[1]), "=r"((r)[2]), "=r"((r)[3]) : "r"(addr))

#define MMA_BF16(d, a, b0, b1) \
    asm volatile("mma.sync.aligned.m16n8k16.row.col.f32.bf16.bf16.f32 " \
        "{%0,%1,%2,%3}, {%4,%5,%6,%7}, {%8,%9}, {%0,%1,%2,%3};" \
        : "+f"((d)[0]), "+f"((d)[1]), "+f"((d)[2]), "+f"((d)[3]) \
        : "r"((a)[0]), "r"((a)[1]), "r"((a)[2]), "r"((a)[3]), "r"(b0), "r"(b1))

#define CP16(dst, src) \
    asm volatile("cp.async.cg.shared.global [%0], [%1], 16;" \
        :: "r"(dst), "l"(src) : "memory")
#define CP_COMMIT() asm volatile("cp.async.commit_group;" ::: "memory")
#define CP_WAIT1()  asm volatile("cp.async.wait_group 1;" ::: "memory")
#define CP_WAIT2()  asm volatile("cp.async.wait_group 2;" ::: "memory")

__device__ __forceinline__ uint32_t pack2(__nv_bfloat16 a, __nv_bfloat16 b) {
    return (uint32_t)__bfloat16_as_ushort(a) |
           ((uint32_t)__bfloat16_as_ushort(b) << 16);
}

__device__ __forceinline__ void cvt4(float4 v, uint2& h, uint2& l) {
    __nv_bfloat16 h0 = __float2bfloat16_rn(v.x);
    __nv_bfloat16 h1 = __float2bfloat16_rn(v.y);
    __nv_bfloat16 h2 = __float2bfloat16_rn(v.z);
    __nv_bfloat16 h3 = __float2bfloat16_rn(v.w);
    __nv_bfloat16 l0 = __float2bfloat16_rn(v.x - __bfloat162float(h0));
    __nv_bfloat16 l1 = __float2bfloat16_rn(v.y - __bfloat162float(h1));
    __nv_bfloat16 l2 = __float2bfloat16_rn(v.z - __bfloat162float(h2));
    __nv_bfloat16 l3 = __float2bfloat16_rn(v.w - __bfloat162float(h3));
    h.x = pack2(h0, h1); h.y = pack2(h2, h3);
    l.x = pack2(l0, l1); l.y = pack2(l2, l3);
}

__device__ __forceinline__ uint32_t hi_lo_pack(float a, float b, uint32_t& lo) {
    __nv_bfloat16 ha = __float2bfloat16_rn(a);
    __nv_bfloat16 hb = __float2bfloat16_rn(b);
    lo = pack2(__float2bfloat16_rn(a - __bfloat162float(ha)),
               __float2bfloat16_rn(b - __bfloat162float(hb)));
    return pack2(ha, hb);
}

// ---------------------------------------------------------------------------
// Fused one-shot f32 -> bf16 hi/lo conversion of all five tensors
// ---------------------------------------------------------------------------
#define XF4 (M_ROWS * D_MODEL / 4)   // 1048576
#define WF4 (DSQ / 4)                // 262144

__global__ void cvt_all(
    const float* __restrict__ x,  const float* __restrict__ wq,
    const float* __restrict__ wk, const float* __restrict__ wv,
    const float* __restrict__ wo,
    __nv_bfloat16* __restrict__ xh,  __nv_bfloat16* __restrict__ xl,
    __nv_bfloat16* __restrict__ wh,  __nv_bfloat16* __restrict__ wl,
    __nv_bfloat16* __restrict__ woh, __nv_bfloat16* __restrict__ wol)
{
    const int i = blockIdx.x * blockDim.x + threadIdx.x;
    const float* src; __nv_bfloat16 *oh, *ol; int j;
    if (i < XF4)              { src = x;  oh = xh;  ol = xl;  j = i; }
    else if (i < XF4 + WF4)   { src = wq; oh = wh;  ol = wl;  j = i - XF4; }
    else if (i < XF4 + 2*WF4) { src = wk; oh = wh + DSQ;  ol = wl + DSQ;  j = i - XF4 - WF4; }
    else if (i < XF4 + 3*WF4) { src = wv; oh = wh + 2*DSQ; ol = wl + 2*DSQ; j = i - XF4 - 2*WF4; }
    else if (i < XF4 + 4*WF4) { src = wo; oh = woh; ol = wol; j = i - XF4 - 3*WF4; }
    else return;
    float4 v = reinterpret_cast<const float4*>(src)[j];
    uint2 hh, ll;
    cvt4(v, hh, ll);
    reinterpret_cast<uint2*>(oh)[j] = hh;
    reinterpret_cast<uint2*>(ol)[j] = ll;
}

// ===========================================================================
// mma.sync bf16x3 GEMM, pre-split inputs, 4-stage cp.async (BK=16).
// CTA 128x128, 8 warps, warp tile 64x32, 2 CTAs/SM.
// ===========================================================================
#define ROWB    48                     // 16 bf16 = 32B + 16B pad
#define T_AH    0
#define T_AL    6144
#define T_BH    12288
#define T_BL    18432
#define STAGE_B 24576
#define GEMM_SMEM_BYTES (4 * STAGE_B)  // 98304

template <bool HAS_BIAS, bool OUT_BF16, bool SCALE_Q8>
__global__ void __launch_bounds__(256, 2) mma_gemm(
    const __nv_bfloat16* __restrict__ Ah, const __nv_bfloat16* __restrict__ Al,
    const __nv_bfloat16* __restrict__ Wh, const __nv_bfloat16* __restrict__ Wl,
    const float* __restrict__ bias,
    float* __restrict__ C,
    __nv_bfloat16* __restrict__ Ch, __nv_bfloat16* __restrict__ Cl,
    int K, int ldc)
{
    extern __shared__ __align__(128) char smem[];
    const uint32_t sbase = smem_u32(smem);
    const int tid  = threadIdx.x;
    const int lane = tid & 31;
    const int bx   = blockIdx.x;
    const int bm   = blockIdx.y * 128;
    const int bn   = (bx & 7) * 128;
    const int cn   = (bx >> 3) * D_MODEL + bn;
    const size_t woff = (size_t)(bx >> 3) * DSQ;

    const int wm = (tid >> 7) * 64;
    const int wn = ((tid >> 5) & 3) * 32;

    const uint32_t a_off = (uint32_t)(wm + (lane & 15)) * ROWB + (lane >> 4) * 16;
    const uint32_t b_off = (uint32_t)(wn + (lane >> 4) * 8 + (lane & 7)) * ROWB
                           + ((lane >> 3) & 1) * 16;

    // Loader: thread -> row lr (0..127), 16B granule lg (0/1)
    const int lr = tid >> 1;
    const int lg = (tid & 1) * 8;              // element offset
    const __nv_bfloat16* pAh = Ah + (size_t)(bm + lr) * K + lg;
    const __nv_bfloat16* pAl = Al + (size_t)(bm + lr) * K + lg;
    const __nv_bfloat16* pWh = Wh + woff + (size_t)(bn + lr) * K + lg;
    const __nv_bfloat16* pWl = Wl + woff + (size_t)(bn + lr) * K + lg;
    const uint32_t soff = (uint32_t)lr * ROWB + (tid & 1) * 16;

    float acc[4][4][4];
#pragma unroll
    for (int i = 0; i < 4; i++)
#pragma unroll
        for (int j = 0; j < 4; j++)
#pragma unroll
            for (int r = 0; r < 4; r++) acc[i][j][r] = 0.f;

    const int nch = K / 16;                    // 64

    // prologue: chunks 0..2 -> stages 0..2
#pragma unroll
    for (int c = 0; c < 3; c++) {
        const uint32_t sb = sbase + c * STAGE_B;
        const int k0 = c * 16;
        CP16(sb + T_AH + soff, pAh + k0);
        CP16(sb + T_AL + soff, pAl + k0);
        CP16(sb + T_BH + soff, pWh + k0);
        CP16(sb + T_BL + soff, pWl + k0);
        CP_COMMIT();
    }

    for (int c = 0; c < nch; c++) {
        CP_WAIT2();
        __syncthreads();

        // issue chunk c+3 into stage (c+3)&3 (buffer of c-1, compute done)
        if (c + 3 < nch) {
            const uint32_t sb = sbase + ((c + 3) & 3) * STAGE_B;
            const int k0 = (c + 3) * 16;
            CP16(sb + T_AH + soff, pAh + k0);
            CP16(sb + T_AL + soff, pAl + k0);
            CP16(sb + T_BH + soff, pWh + k0);
            CP16(sb + T_BL + soff, pWl + k0);
        }
        CP_COMMIT();   // uniform commit keeps wait_group arithmetic exact

        const uint32_t stb = sbase + (c & 3) * STAGE_B;
        uint32_t ah[4][4], al[4][4];
#pragma unroll
        for (int mf = 0; mf < 4; mf++) {
            LDM4(ah[mf], stb + T_AH + a_off + mf * (16 * ROWB));
            LDM4(al[mf], stb + T_AL + a_off + mf * (16 * ROWB));
        }
        uint32_t bh[2][4], bl[2][4];
#pragma unroll
        for (int p = 0; p < 2; p++) {
            LDM4(bh[p], stb + T_BH + b_off + p * (16 * ROWB));
            LDM4(bl[p], stb + T_BL + b_off + p * (16 * ROWB));
        }
#pragma unroll
        for (int mf = 0; mf < 4; mf++) {
#pragma unroll
            for (int nf = 0; nf < 4; nf++) {
                const uint32_t b0h = bh[nf >> 1][(nf & 1) * 2];
                const uint32_t b1h = bh[nf >> 1][(nf & 1) * 2 + 1];
                const uint32_t b0l = bl[nf >> 1][(nf & 1) * 2];
                const uint32_t b1l = bl[nf >> 1][(nf & 1) * 2 + 1];
                MMA_BF16(acc[mf][nf], ah[mf], b0h, b1h);
                MMA_BF16(acc[mf][nf], ah[mf], b0l, b1l);
                MMA_BF16(acc[mf][nf], al[mf], b0h, b1h);
            }
        }
    }

    const int g  = lane >> 2;
    const int t2 = (lane & 3) * 2;
    const float sc = (SCALE_Q8 && bx < 8) ? 0.125f : 1.0f;
#pragma unroll
    for (int mf = 0; mf < 4; mf++) {
#pragma unroll
        for (int nf = 0; nf < 4; nf++) {
            const int m = bm + wm + mf * 16 + g;
            const int n = cn + wn + nf * 8 + t2;
            float2 v0, v1;
            v0.x = acc[mf][nf][0]; v0.y = acc[mf][nf][1];
            v1.x = acc[mf][nf][2]; v1.y = acc[mf][nf][3];
            if (OUT_BF16) {
                v0.x *= sc; v0.y *= sc; v1.x *= sc; v1.y *= sc;
                uint32_t l0_, l1_;
                uint32_t h0_ = hi_lo_pack(v0.x, v0.y, l0_);
                uint32_t h1_ = hi_lo_pack(v1.x, v1.y, l1_);
                *reinterpret_cast<uint32_t*>(&Ch[(size_t)m * ldc + n]) = h0_;
                *reinterpret_cast<uint32_t*>(&Cl[(size_t)m * ldc + n]) = l0_;
                *reinterpret_cast<uint32_t*>(&Ch[(size_t)(m + 8) * ldc + n]) = h1_;
                *reinterpret_cast<uint32_t*>(&Cl[(size_t)(m + 8) * ldc + n]) = l1_;
            } else {
                if (HAS_BIAS) {
                    const float2 bv = *reinterpret_cast<const float2*>(&bias[n]);
                    v0.x += bv.x; v0.y += bv.y;
                    v1.x += bv.x; v1.y += bv.y;
                }
                *reinterpret_cast<float2*>(&C[(size_t)m * ldc + n]) = v0;
                *reinterpret_cast<float2*>(&C[(size_t)(m + 8) * ldc + n]) = v1;
            }
        }
    }
}

// ===========================================================================
// Tensor-core causal flash attention, 3-stage cp.async KV ring.
// ===========================================================================
#define FROWB 144
#define KV_KH 0
#define KV_KL 9216
#define KV_VH 18432
#define KV_VL 27648
#define KV_STAGE 36864
#define SQH   0
#define SQL   18432
#define FLASH_SMEM_BYTES (3 * KV_STAGE)   // 110592

__global__ void __launch_bounds__(256) flash_mma(
    const __nv_bfloat16* __restrict__ qkvh,
    const __nv_bfloat16* __restrict__ qkvl,
    __nv_bfloat16* __restrict__ atth,
    __nv_bfloat16* __restrict__ attl)
{
    extern __shared__ __align__(128) char smem[];
    const uint32_t sbase = smem_u32(smem);
    const int tid  = threadIdx.x;
    const int lane = tid & 31;
    const int w    = tid >> 5;
    const int qt   = (gridDim.x - 1) - blockIdx.x;
    const int h    = blockIdx.y;
    const int b    = blockIdx.z;

    const size_t head_base = (size_t)b * S_LEN * QKV_LD + (size_t)h * HD;

    // ---- Stage Q hi/lo into stage0 area (before KV prologue), load A-frags ----
    {
        const int r = tid >> 1;
        const int g0 = (tid & 1) * 4;
        const __nv_bfloat16* qrh = qkvh + head_base + (size_t)(qt * 128 + r) * QKV_LD;
        const __nv_bfloat16* qrl = qkvl + head_base + (size_t)(qt * 128 + r) * QKV_LD;
#pragma unroll
        for (int t = 0; t < 4; t++) {
            const int gg = g0 + t;
            const uint32_t off = (uint32_t)r * FROWB + gg * 16;
            *reinterpret_cast<uint4*>(smem + SQH + off) =
                *reinterpret_cast<const uint4*>(qrh + gg * 8);
            *reinterpret_cast<uint4*>(smem + SQL + off) =
                *reinterpret_cast<const uint4*>(qrl + gg * 8);
        }
    }
    __syncthreads();

    uint32_t qh[4][4], ql[4][4];
    {
        const uint32_t a_off = (uint32_t)(w * 16 + (lane & 15)) * FROWB
                               + ((lane >> 4) * 8) * 2;
#pragma unroll
        for (int ks = 0; ks < 4; ks++) {
            LDM4(qh[ks], sbase + SQH + a_off + ks * 32);
            LDM4(ql[ks], sbase + SQL + a_off + ks * 32);
        }
    }
    __syncthreads();

    float o[8][4];
#pragma unroll
    for (int nf = 0; nf < 8; nf++)
#pragma unroll
        for (int r = 0; r < 4; r++) o[nf][r] = 0.f;
    float m0 = -1e30f, m1 = -1e30f, l0 = 0.f, l1 = 0.f;

    const int g  = lane >> 2;
    const int t2 = (lane & 3) * 2;
    const int wrow = qt * 128 + w * 16;
    const int row0 = wrow + g;
    const int row1 = row0 + 8;

    const uint32_t kb_off = (uint32_t)((lane >> 4) * 8 + (lane & 7)) * FROWB
                            + (((lane >> 3) & 1) * 8) * 2;
    const uint32_t vt_row = (uint32_t)(lane & 15) * FROWB + ((lane >> 4) * 8) * 2;

    // KV loader mapping
    const int klr = tid >> 2;            // row 0..63
    const int kg0 = (tid & 3) * 2;       // granule base

    const int kt_end = 2 * qt + 1;       // >= 1 always

    // prologue: kt=0 -> buf0, kt=1 -> buf1
#pragma unroll
    for (int c = 0; c < 2; c++) {
        const uint32_t sb = sbase + c * KV_STAGE;
        const size_t rowb = head_base + (size_t)(c * 64 + klr) * QKV_LD;
#pragma unroll
        for (int t = 0; t < 2; t++) {
            const int gg = kg0 + t;
            const uint32_t off = (uint32_t)klr * FROWB + gg * 16;
            CP16(sb + KV_KH + off, qkvh + rowb + D_MODEL + gg * 8);
            CP16(sb + KV_KL + off, qkvl + rowb + D_MODEL + gg * 8);
            CP16(sb + KV_VH + off, qkvh + rowb + 2 * D_MODEL + gg * 8);
            CP16(sb + KV_VL + off, qkvl + rowb + 2 * D_MODEL + gg * 8);
        }
        CP_COMMIT();
    }

    for (int kt = 0; kt <= kt_end; kt++) {
        CP_WAIT1();
        __syncthreads();

        // issue kt+2 into buffer (kt+2)%3 (kt-1's buffer; compute done)
        if (kt + 2 <= kt_end) {
            const uint32_t sb = sbase + ((kt + 2) % 3) * KV_STAGE;
            const size_t rowb = head_base + (size_t)((kt + 2) * 64 + klr) * QKV_LD;
#pragma unroll
            for (int t = 0; t < 2; t++) {
                const int gg = kg0 + t;
                const uint32_t off = (uint32_t)klr * FROWB + gg * 16;
                CP16(sb + KV_KH + off, qkvh + rowb + D_MODEL + gg * 8);
                CP16(sb + KV_KL + off, qkvl + rowb + D_MODEL + gg * 8);
                CP16(sb + KV_VH + off, qkvh + rowb + 2 * D_MODEL + gg * 8);
                CP16(sb + KV_VL + off, qkvl + rowb + 2 * D_MODEL + gg * 8);
            }
        }
        CP_COMMIT();

        const bool active = (kt * 64 <= wrow + 15);
        if (active) {
            const uint32_t stb = sbase + (kt % 3) * KV_STAGE;
            float s[8][4];
#pragma unroll
            for (int nf = 0; nf < 8; nf++)
#pragma unroll
                for (int r = 0; r < 4; r++) s[nf][r] = 0.f;

#pragma unroll
            for (int ks = 0; ks < 4; ks++) {
#pragma unroll
                for (int p = 0; p < 4; p++) {
                    uint32_t kh[4], kl[4];
                    LDM4(kh, stb + KV_KH + kb_off + p * (16 * FROWB) + ks * 32);
                    LDM4(kl, stb + KV_KL + kb_off + p * (16 * FROWB) + ks * 32);
                    MMA_BF16(s[2 * p],     qh[ks], kh[0], kh[1]);
                    MMA_BF16(s[2 * p],     qh[ks], kl[0], kl[1]);
                    MMA_BF16(s[2 * p],     ql[ks], kh[0], kh[1]);
                    MMA_BF16(s[2 * p + 1], qh[ks], kh[2], kh[3]);
                    MMA_BF16(s[2 * p + 1], qh[ks], kl[2], kl[3]);
                    MMA_BF16(s[2 * p + 1], ql[ks], kh[2], kh[3]);
                }
            }

            if (kt * 64 + 63 > wrow) {
#pragma unroll
                for (int nf = 0; nf < 8; nf++) {
                    const int c0 = kt * 64 + nf * 8 + t2;
                    if (c0     > row0) s[nf][0] = -1e30f;
                    if (c0 + 1 > row0) s[nf][1] = -1e30f;
                    if (c0     > row1) s[nf][2] = -1e30f;
                    if (c0 + 1 > row1) s[nf][3] = -1e30f;
                }
            }

            float mx0 = s[0][0], mx1 = s[0][2];
#pragma unroll
            for (int nf = 0; nf < 8; nf++) {
                mx0 = fmaxf(mx0, fmaxf(s[nf][0], s[nf][1]));
                mx1 = fmaxf(mx1, fmaxf(s[nf][2], s[nf][3]));
            }
            mx0 = fmaxf(mx0, __shfl_xor_sync(0xffffffffu, mx0, 1));
            mx0 = fmaxf(mx0, __shfl_xor_sync(0xffffffffu, mx0, 2));
            mx1 = fmaxf(mx1, __shfl_xor_sync(0xffffffffu, mx1, 1));
            mx1 = fmaxf(mx1, __shfl_xor_sync(0xffffffffu, mx1, 2));

            const float nm0 = fmaxf(m0, mx0), nm1 = fmaxf(m1, mx1);
            const float a0 = __expf(m0 - nm0), a1 = __expf(m1 - nm1);
            m0 = nm0; m1 = nm1;

            float sum0 = 0.f, sum1 = 0.f;
#pragma unroll
            for (int nf = 0; nf < 8; nf++) {
                s[nf][0] = __expf(s[nf][0] - nm0);
                s[nf][1] = __expf(s[nf][1] - nm0);
                s[nf][2] = __expf(s[nf][2] - nm1);
                s[nf][3] = __expf(s[nf][3] - nm1);
                sum0 += s[nf][0] + s[nf][1];
                sum1 += s[nf][2] + s[nf][3];
            }
            sum0 += __shfl_xor_sync(0xffffffffu, sum0, 1);
            sum0 += __shfl_xor_sync(0xffffffffu, sum0, 2);
            sum1 += __shfl_xor_sync(0xffffffffu, sum1, 1);
            sum1 += __shfl_xor_sync(0xffffffffu, sum1, 2);
            l0 = l0 * a0 + sum0;
            l1 = l1 * a1 + sum1;

#pragma unroll
            for (int nf = 0; nf < 8; nf++) {
                o[nf][0] *= a0; o[nf][1] *= a0;
                o[nf][2] *= a1; o[nf][3] *= a1;
            }

#pragma unroll
            for (int j = 0; j < 4; j++) {
                uint32_t ph[4], pl[4];
                ph[0] = hi_lo_pack(s[2 * j][0],     s[2 * j][1],     pl[0]);
                ph[1] = hi_lo_pack(s[2 * j][2],     s[2 * j][3],     pl[1]);
                ph[2] = hi_lo_pack(s[2 * j + 1][0], s[2 * j + 1][1], pl[2]);
                ph[3] = hi_lo_pack(s[2 * j + 1][2], s[2 * j + 1][3], pl[3]);

                const uint32_t vbase = (uint32_t)(j * 16) * FROWB + vt_row;
#pragma unroll
                for (int hg = 0; hg < 4; hg++) {
                    uint32_t vh[4], vl[4];
                    LDM4T(vh, stb + KV_VH + vbase + hg * 32);
                    LDM4T(vl, stb + KV_VL + vbase + hg * 32);
                    MMA_BF16(o[2 * hg],     ph, vh[0], vh[1]);
                    MMA_BF16(o[2 * hg],     ph, vl[0], vl[1]);
                    MMA_BF16(o[2 * hg],     pl, vh[0], vh[1]);
                    MMA_BF16(o[2 * hg + 1], ph, vh[2], vh[3]);
                    MMA_BF16(o[2 * hg + 1], ph, vl[2], vl[3]);
                    MMA_BF16(o[2 * hg + 1], pl, vh[2], vh[3]);
                }
            }
        }
    }

    // ---- Normalize and write attn as bf16 hi/lo ----
    const float inv0 = 1.f / l0, inv1 = 1.f / l1;
    const size_t ob = ((size_t)b * S_LEN + qt * 128 + w * 16) * D_MODEL
                      + (size_t)h * HD;
#pragma unroll
    for (int nf = 0; nf < 8; nf++) {
        const int c = nf * 8 + t2;
        uint32_t lo0, lo1;
        uint32_t hi0 = hi_lo_pack(o[nf][0] * inv0, o[nf][1] * inv0, lo0);
        uint32_t hi1 = hi_lo_pack(o[nf][2] * inv1, o[nf][3] * inv1, lo1);
        *reinterpret_cast<uint32_t*>(&atth[ob + (size_t)g * D_MODEL + c]) = hi0;
        *reinterpret_cast<uint32_t*>(&attl[ob + (size_t)g * D_MODEL + c]) = lo0;
        *reinterpret_cast<uint32_t*>(&atth[ob + (size_t)(g + 8) * D_MODEL + c]) = hi1;
        *reinterpret_cast<uint32_t*>(&attl[ob + (size_t)(g + 8) * D_MODEL + c]) = lo1;
    }
}

// ---------------------------------------------------------------------------
extern "C" void kernel_launch(void* const* d_in, const int* in_sizes, int n_in,
                              void* d_out, int out_size)
{
    const float* x    = (const float*)d_in[0];
    const float* wq   = (const float*)d_in[1];
    const float* wk   = (const float*)d_in[2];
    const float* wv   = (const float*)d_in[3];
    const float* wo_w = (const float*)d_in[4];
    const float* wo_b = (const float*)d_in[5];
    float* out = (float*)d_out;

    __nv_bfloat16 *xh, *xl, *wh, *wl, *woh, *wol, *qkvh, *qkvl, *atth, *attl;
    cudaGetSymbolAddress((void**)&xh,   g_xh);
    cudaGetSymbolAddress((void**)&xl,   g_xl);
    cudaGetSymbolAddress((void**)&wh,   g_wh);
    cudaGetSymbolAddress((void**)&wl,   g_wl);
    cudaGetSymbolAddress((void**)&woh,  g_woh);
    cudaGetSymbolAddress((void**)&wol,  g_wol);
    cudaGetSymbolAddress((void**)&qkvh, g_qkvh);
    cudaGetSymbolAddress((void**)&qkvl, g_qkvl);
    cudaGetSymbolAddress((void**)&atth, g_atth);
    cudaGetSymbolAddress((void**)&attl, g_attl);

    static bool attr_done = false;
    if (!attr_done) {
        cudaFuncSetAttribute((const void*)mma_gemm<false, true, true>,
                             cudaFuncAttributeMaxDynamicSharedMemorySize,
                             GEMM_SMEM_BYTES);
        cudaFuncSetAttribute((const void*)mma_gemm<true, false, false>,
                             cudaFuncAttributeMaxDynamicSharedMemorySize,
                             GEMM_SMEM_BYTES);
        cudaFuncSetAttribute((const void*)flash_mma,
                             cudaFuncAttributeMaxDynamicSharedMemorySize,
                             FLASH_SMEM_BYTES);
        attr_done = true;
    }

    // Fused one-shot conversions
    const int total4 = XF4 + 4 * WF4;
    cvt_all<<<(total4 + 255) / 256, 256>>>(x, wq, wk, wv, wo_w,
                                           xh, xl, wh, wl, woh, wol);

    // Fused QKV projection -> bf16 hi/lo (Q pre-scaled x0.125)
    const dim3 qkv_grid(24, M_ROWS / 128);
    mma_gemm<false, true, true><<<qkv_grid, 256, GEMM_SMEM_BYTES>>>(
        xh, xl, wh, wl, nullptr, nullptr, qkvh, qkvl, D_MODEL, QKV_LD);

    // Tensor-core causal flash attention -> attn bf16 hi/lo
    const dim3 flash_grid(S_LEN / 128, NHEAD, B_SZ);
    flash_mma<<<flash_grid, 256, FLASH_SMEM_BYTES>>>(qkvh, qkvl, atth, attl);

    // Output projection (f32 out, bias)
    const dim3 o_grid(8, M_ROWS / 128);
    mma_gemm<true, false, false><<<o_grid, 256, GEMM_SMEM_BYTES>>>(
        atth, attl, woh, wol, wo_b, out, nullptr, nullptr, D_MODEL, D_MODEL);
}